// round 3
// baseline (speedup 1.0000x reference)
#include <cuda_runtime.h>
#include <math.h>

#define Bn  2
#define Sn  256
#define INn 80
#define Hn  128
#define G4  512
#define F2n 256
#define NCn 40
#define Wn  64
#define PHn 100

// ---------------- scratch (device globals; no allocation allowed) ----------
__device__ float g_pre[2][Bn][Sn][G4];     // [dir][b][s][gate] (reused per layer)
__device__ float g_out0[Bn][Sn][F2n];      // layer-0 output (fwd||bwd)
__device__ float g_rnn [Bn][Sn][F2n];      // layer-1 output = rnn_out
__device__ float g_cum [Bn][Sn][F2n];      // cumsum over s
__device__ float g_u[Bn][Sn][PHn];         // W1d . prelu(rnn)   (d-part, index j)
__device__ float g_v[Bn][Sn][PHn];         // W1e . prelu(rnn)   (e-part, index i)
__device__ float g_sband[Bn][Sn][Wn];      // scores[b][start+k][i], start=max(0,i-64)
__device__ int   g_bp[Bn][Sn];             // backpointers

__device__ __forceinline__ float sigf(float x) { return 1.0f / (1.0f + expf(-x)); }

// ---------------------------------------------------------------------------
// pre[dir][b][s][g] = bias[g] + dot(W_ih[g,:], input[b][s,:])
// layer==0: input = x (IN=80); layer==1: input = g_out0 (256)
// ---------------------------------------------------------------------------
__global__ void pre_kernel(const float* __restrict__ x, int layer,
                           const float* __restrict__ wf, const float* __restrict__ bf,
                           const float* __restrict__ wb, const float* __restrict__ bb)
{
    int s = blockIdx.x, b = blockIdx.y, d = blockIdx.z;
    int g = threadIdx.x;                       // 512 threads
    int in_dim = layer ? F2n : INn;
    const float* row = layer ? &g_out0[b][s][0] : (x + (b * Sn + s) * INn);

    __shared__ float xs[F2n];
    for (int i = g; i < in_dim; i += blockDim.x) xs[i] = row[i];
    __syncthreads();

    const float* w = (d ? wb : wf) + g * in_dim;
    float acc = (d ? bb : bf)[g];
    #pragma unroll 8
    for (int i = 0; i < in_dim; i++) acc += w[i] * xs[i];
    g_pre[d][b][s][g] = acc;
}

// ---------------------------------------------------------------------------
// Sequential LSTM scan, one CTA per (dir, batch). 512 threads = one per gate row.
// ---------------------------------------------------------------------------
__global__ void scan_kernel(int layer,
                            const float* __restrict__ whh_f,
                            const float* __restrict__ whh_b)
{
    int d = blockIdx.x, b = blockIdx.y;
    int tid = threadIdx.x;                     // 512
    __shared__ __align__(16) float hsm[Hn];
    __shared__ float gall[G4];

    const float* whh = d ? whh_b : whh_f;
    const float4* wrow = (const float4*)(whh + tid * Hn);
    float* out = layer ? &g_rnn[0][0][0] : &g_out0[0][0][0];

    float c = 0.f;
    if (tid < Hn) hsm[tid] = 0.f;
    __syncthreads();

    for (int t = 0; t < Sn; t++) {
        int s = d ? (Sn - 1 - t) : t;
        float acc = g_pre[d][b][s][tid];
        const float4* h4 = (const float4*)hsm;
        #pragma unroll 8
        for (int k = 0; k < Hn / 4; k++) {
            float4 w = wrow[k]; float4 h = h4[k];
            acc += w.x * h.x + w.y * h.y + w.z * h.z + w.w * h.w;
        }
        gall[tid] = acc;
        __syncthreads();
        if (tid < Hn) {
            float gi = gall[tid], gf = gall[Hn + tid];
            float gg = gall[2 * Hn + tid], go = gall[3 * Hn + tid];
            c = sigf(gf) * c + sigf(gi) * tanhf(gg);
            float h = sigf(go) * tanhf(c);
            hsm[tid] = h;
            out[(b * Sn + s) * F2n + d * Hn + tid] = h;
        }
        __syncthreads();
    }
}

// ---------------------------------------------------------------------------
// cum[b][s][t] = prefix-sum over s of rnn_out
// ---------------------------------------------------------------------------
__global__ void cum_kernel()
{
    int b = blockIdx.x, t = threadIdx.x;       // 256 threads
    float acc = 0.f;
    for (int s = 0; s < Sn; s++) { acc += g_rnn[b][s][t]; g_cum[b][s][t] = acc; }
}

// ---------------------------------------------------------------------------
// Per-position work: u/v projections for the score MLP + cls/bin MLP outputs.
// One CTA per (b,s), 128 threads.
// ---------------------------------------------------------------------------
__global__ void feat_kernel(const float* __restrict__ a_s0p, const float* __restrict__ w_s1,
                            const float* __restrict__ a_c0p, const float* __restrict__ w_c1,
                            const float* __restrict__ b_c1,  const float* __restrict__ a_c1p,
                            const float* __restrict__ w_c2,  const float* __restrict__ b_c2,
                            const float* __restrict__ a_b0p, const float* __restrict__ w_b1,
                            const float* __restrict__ b_b1,  const float* __restrict__ a_b1p,
                            const float* __restrict__ w_b2,  const float* __restrict__ b_b2,
                            float* __restrict__ out)
{
    int s = blockIdx.x, b = blockIdx.y, tid = threadIdx.x;   // 128 threads
    __shared__ float prs[F2n], prc[F2n], prb[F2n];
    __shared__ float hc[80], hb[80];
    float as0 = *a_s0p, ac0 = *a_c0p, ac1 = *a_c1p, ab0 = *a_b0p, ab1 = *a_b1p;

    for (int i = tid; i < F2n; i += 128) {
        float xv = g_rnn[b][s][i];
        prs[i] = xv >= 0.f ? xv : as0 * xv;
        prc[i] = xv >= 0.f ? xv : ac0 * xv;
        prb[i] = xv >= 0.f ? xv : ab0 * xv;
    }
    __syncthreads();

    if (tid < PHn) {
        float au = 0.f, av = 0.f;
        const float* wu = w_s1 + tid * 768 + 256;   // d-part columns
        const float* wv = w_s1 + tid * 768 + 512;   // e-part columns
        #pragma unroll 8
        for (int i = 0; i < F2n; i++) { au += wu[i] * prs[i]; av += wv[i] * prs[i]; }
        g_u[b][s][tid] = au;
        g_v[b][s][tid] = av;
    }
    if (tid < 80) {
        float a1 = b_c1[tid], a2 = b_b1[tid];
        const float* w1 = w_c1 + tid * F2n;
        const float* w2 = w_b1 + tid * F2n;
        #pragma unroll 8
        for (int i = 0; i < F2n; i++) { a1 += w1[i] * prc[i]; a2 += w2[i] * prb[i]; }
        hc[tid] = a1 >= 0.f ? a1 : ac1 * a1;
        hb[tid] = a2 >= 0.f ? a2 : ab1 * a2;
    }
    __syncthreads();
    if (tid < NCn) {
        float acc = b_c2[tid];
        const float* w = w_c2 + tid * 80;
        #pragma unroll 8
        for (int i = 0; i < 80; i++) acc += w[i] * hc[i];
        out[(b * Sn + s) * NCn + tid] = acc;
    }
    if (tid < 2) {
        float acc = b_b2[tid];
        const float* w = w_b2 + tid * 80;
        for (int i = 0; i < 80; i++) acc += w[i] * hb[i];
        out[Bn * Sn * NCn + (b * Sn + s) * 2 + tid] = acc;
    }
}

// ---------------------------------------------------------------------------
// Banded scores: sband[b][i][k] = score(j -> i), j = max(0,i-64)+k, j < i.
// hidden = b_s1 + u[j] + v[i] + W1c . prelu(cum[i]-cum[j]);
// score  = b_s2 + w_s2 . prelu(hidden)
// One CTA per (k, i, b), 128 threads.
// ---------------------------------------------------------------------------
__global__ void sband_kernel(const float* __restrict__ a_s0p, const float* __restrict__ w_s1,
                             const float* __restrict__ b_s1,  const float* __restrict__ a_s1p,
                             const float* __restrict__ w_s2,  const float* __restrict__ b_s2)
{
    int k = blockIdx.x, i = blockIdx.y, b = blockIdx.z, tid = threadIdx.x;
    if (i == 0) return;
    int start = i - Wn; if (start < 0) start = 0;
    int j = start + k;
    if (j >= i) return;

    __shared__ __align__(16) float pd[F2n];
    __shared__ float red[128];
    float as0 = *a_s0p;
    for (int t = tid; t < F2n; t += 128) {
        float cdiff = g_cum[b][i][t] - g_cum[b][j][t];
        pd[t] = cdiff >= 0.f ? cdiff : as0 * cdiff;
    }
    __syncthreads();

    float val = 0.f;
    if (tid < PHn) {
        float acc = b_s1[tid] + g_u[b][j][tid] + g_v[b][i][tid];
        const float4* w4 = (const float4*)(w_s1 + tid * 768);   // c-part columns [0,256)
        const float4* p4 = (const float4*)pd;
        #pragma unroll 8
        for (int t = 0; t < F2n / 4; t++) {
            float4 wv = w4[t], pv = p4[t];
            acc += wv.x * pv.x + wv.y * pv.y + wv.z * pv.z + wv.w * pv.w;
        }
        float as1 = *a_s1p;
        float h = acc >= 0.f ? acc : as1 * acc;
        val = h * w_s2[tid];
    }
    red[tid] = val;
    __syncthreads();
    for (int off = 64; off > 0; off >>= 1) {
        if (tid < off) red[tid] += red[tid + off];
        __syncthreads();
    }
    if (tid == 0) g_sband[b][i][k] = red[0] + b_s2[0];
}

// ---------------------------------------------------------------------------
// DP over segments + backtrack. Single CTA, 128 threads (= 2 batches x 64 window).
// ---------------------------------------------------------------------------
__global__ void dp_kernel(const int* __restrict__ lengths, float* __restrict__ out)
{
    int tid = threadIdx.x;                     // 128
    __shared__ float best[Bn][Sn];
    __shared__ float wmax[4];
    __shared__ int   warg[4];

    for (int idx = tid; idx < Bn * Sn; idx += 128) ((float*)best)[idx] = 0.f;
    if (tid < Bn) g_bp[tid][0] = 0;
    __syncthreads();

    int b = tid >> 6, k = tid & 63;
    int lane = tid & 31, wid = tid >> 5;       // warps 0,1 -> b=0 ; 2,3 -> b=1

    for (int i = 1; i < Sn; i++) {
        int start = i - Wn; if (start < 0) start = 0;
        int j = start + k;
        float cv = (j < i) ? best[b][j] + g_sband[b][i][k] : -1e9f;
        int cj = j;
        #pragma unroll
        for (int off = 16; off; off >>= 1) {
            float ov = __shfl_down_sync(0xffffffffu, cv, off);
            int   oj = __shfl_down_sync(0xffffffffu, cj, off);
            if (ov > cv || (ov == cv && oj < cj)) { cv = ov; cj = oj; }
        }
        if (lane == 0) { wmax[wid] = cv; warg[wid] = cj; }
        __syncthreads();
        if (tid < Bn) {
            float v0 = wmax[tid * 2], v1 = wmax[tid * 2 + 1];
            int   j0 = warg[tid * 2], j1 = warg[tid * 2 + 1];
            float mv; int mj;
            if (v1 > v0 || (v1 == v0 && j1 < j0)) { mv = v1; mj = j1; }
            else                                   { mv = v0; mj = j0; }
            best[tid][i] = mv;
            g_bp[tid][i] = mj;
        }
        __syncthreads();
    }

    // ---- backtrack ----
    float* bm = out + Bn * Sn * NCn + Bn * Sn * 2;
    for (int idx = tid; idx < Bn * Sn; idx += 128) bm[idx] = 0.f;
    __syncthreads();
    if (tid < Bn) {
        int bb = tid;
        int cur = lengths[bb] - 1;
        float acc = 0.f;
        for (int st = 0; st < Sn; st++) {
            bm[bb * Sn + cur] = 1.0f;
            int prev = g_bp[bb][cur];
            if (cur > 0) {
                int s0 = cur - Wn; if (s0 < 0) s0 = 0;
                acc += g_sband[bb][cur][prev - s0];
                cur = prev;
            }
        }
        out[Bn * Sn * NCn + Bn * Sn * 2 + Bn * Sn + bb] = acc;
    }
}

// ---------------------------------------------------------------------------
extern "C" void kernel_launch(void* const* d_in, const int* in_sizes, int n_in,
                              void* d_out, int out_size)
{
    const float* x        = (const float*)d_in[0];
    const int*   lengths  = (const int*)  d_in[1];
    const float* w_ih_l0f = (const float*)d_in[2];
    const float* w_hh_l0f = (const float*)d_in[3];
    const float* b_l0f    = (const float*)d_in[4];
    const float* w_ih_l0b = (const float*)d_in[5];
    const float* w_hh_l0b = (const float*)d_in[6];
    const float* b_l0b    = (const float*)d_in[7];
    const float* w_ih_l1f = (const float*)d_in[8];
    const float* w_hh_l1f = (const float*)d_in[9];
    const float* b_l1f    = (const float*)d_in[10];
    const float* w_ih_l1b = (const float*)d_in[11];
    const float* w_hh_l1b = (const float*)d_in[12];
    const float* b_l1b    = (const float*)d_in[13];
    const float* a_s0     = (const float*)d_in[14];
    const float* w_s1     = (const float*)d_in[15];
    const float* b_s1     = (const float*)d_in[16];
    const float* a_s1     = (const float*)d_in[17];
    const float* w_s2     = (const float*)d_in[18];
    const float* b_s2     = (const float*)d_in[19];
    const float* a_c0     = (const float*)d_in[20];
    const float* w_c1     = (const float*)d_in[21];
    const float* b_c1     = (const float*)d_in[22];
    const float* a_c1     = (const float*)d_in[23];
    const float* w_c2     = (const float*)d_in[24];
    const float* b_c2     = (const float*)d_in[25];
    const float* a_b0     = (const float*)d_in[26];
    const float* w_b1     = (const float*)d_in[27];
    const float* b_b1     = (const float*)d_in[28];
    const float* a_b1     = (const float*)d_in[29];
    const float* w_b2     = (const float*)d_in[30];
    const float* b_b2     = (const float*)d_in[31];
    float* out = (float*)d_out;

    // layer 0
    pre_kernel<<<dim3(Sn, Bn, 2), 512>>>(x, 0, w_ih_l0f, b_l0f, w_ih_l0b, b_l0b);
    scan_kernel<<<dim3(2, Bn), 512>>>(0, w_hh_l0f, w_hh_l0b);
    // layer 1
    pre_kernel<<<dim3(Sn, Bn, 2), 512>>>(x, 1, w_ih_l1f, b_l1f, w_ih_l1b, b_l1b);
    scan_kernel<<<dim3(2, Bn), 512>>>(1, w_hh_l1f, w_hh_l1b);
    // cumsum + per-position projections / MLP heads
    cum_kernel<<<Bn, F2n>>>();
    feat_kernel<<<dim3(Sn, Bn), 128>>>(a_s0, w_s1, a_c0, w_c1, b_c1, a_c1, w_c2, b_c2,
                                       a_b0, w_b1, b_b1, a_b1, w_b2, b_b2, out);
    // banded pair scores
    sband_kernel<<<dim3(Wn, Sn, Bn), 128>>>(a_s0, w_s1, b_s1, a_s1, w_s2, b_s2);
    // DP + backtrack
    dp_kernel<<<1, 128>>>(lengths, out);
}

// round 4
// speedup vs baseline: 4.3396x; 4.3396x over previous
#include <cuda_runtime.h>
#include <math.h>

#define Bn  2
#define Sn  256
#define INn 80
#define Hn  128
#define G4  512
#define F2n 256
#define NCn 40
#define Wn  64
#define PHn 100
#define TP  132   // sband smem row pad (t-dim half tile 128 + 4)

// ---------------- scratch (device globals) ---------------------------------
__device__ float4 g_whhP[2][2][Hn][Hn];    // [layer][dir][k][unit] = (Wi,Wf,Wg,Wo)[unit][k]
__device__ float  g_wihT0[2][INn][G4];     // [dir][i][g]
__device__ float  g_wihT1[2][F2n][G4];
__device__ float  g_w1cT[F2n][128];        // [t][ph], ph>=100 zero
__device__ float  g_w1dT[F2n][128];
__device__ float  g_w1eT[F2n][128];
__device__ float  g_wc1T[F2n][80];         // [t][q]
__device__ float  g_wb1T[F2n][80];
__device__ float4 g_preP[2][Bn][Sn][Hn];   // packed gates per unit (reused per layer)
__device__ float  g_out0[Bn][Sn][F2n];
__device__ float  g_rnn [Bn][Sn][F2n];
__device__ float  g_cum [Bn][Sn][F2n];
__device__ float  g_u[Bn][Sn][PHn];
__device__ float  g_v[Bn][Sn][PHn];
__device__ float  g_sband[Bn][Sn][Wn];

__device__ __forceinline__ float sigf(float x) { return 1.0f / (1.0f + expf(-x)); }

// ---------------------------------------------------------------------------
// Weight prep: transposed / packed layouts (coalesced consumers).
// ---------------------------------------------------------------------------
__global__ void prep_whh_kernel(const float* __restrict__ w0f, const float* __restrict__ w0b,
                                const float* __restrict__ w1f, const float* __restrict__ w1b)
{
    int k = blockIdx.x, d = blockIdx.y, l = blockIdx.z, t = threadIdx.x;  // 128 thr
    const float* w = l ? (d ? w1b : w1f) : (d ? w0b : w0f);
    g_whhP[l][d][k][t] = make_float4(w[t * Hn + k], w[(Hn + t) * Hn + k],
                                     (float)w[(2 * Hn + t) * Hn + k], w[(3 * Hn + t) * Hn + k]);
}

__global__ void prep_wih_kernel(const float* __restrict__ w0f, const float* __restrict__ w0b,
                                const float* __restrict__ w1f, const float* __restrict__ w1b)
{
    int idx = blockIdx.x * blockDim.x + threadIdx.x;
    const int N0 = 2 * INn * G4;            // 81920
    const int N1 = 2 * F2n * G4;            // 262144
    if (idx < N0) {
        int d = idx / (INn * G4), r = idx % (INn * G4);
        int i = r / G4, g = r % G4;
        g_wihT0[d][i][g] = (d ? w0b : w0f)[g * INn + i];
    } else if (idx < N0 + N1) {
        int r2 = idx - N0;
        int d = r2 / (F2n * G4), r = r2 % (F2n * G4);
        int i = r / G4, g = r % G4;
        g_wihT1[d][i][g] = (d ? w1b : w1f)[g * F2n + i];
    }
}

__global__ void prep_score_kernel(const float* __restrict__ w_s1,
                                  const float* __restrict__ w_c1,
                                  const float* __restrict__ w_b1)
{
    int idx = blockIdx.x * blockDim.x + threadIdx.x;
    const int NA = F2n * 128;               // 32768 per tensor
    const int NB = F2n * 80;                // 20480
    if (idx < NA) {
        int t = idx >> 7, ph = idx & 127;
        g_w1cT[t][ph] = (ph < PHn) ? w_s1[ph * 768 + t] : 0.f;
    } else if (idx < 2 * NA) {
        int r = idx - NA; int t = r >> 7, ph = r & 127;
        g_w1dT[t][ph] = (ph < PHn) ? w_s1[ph * 768 + 256 + t] : 0.f;
    } else if (idx < 3 * NA) {
        int r = idx - 2 * NA; int t = r >> 7, ph = r & 127;
        g_w1eT[t][ph] = (ph < PHn) ? w_s1[ph * 768 + 512 + t] : 0.f;
    } else if (idx < 3 * NA + NB) {
        int r = idx - 3 * NA; int t = r / 80, q = r % 80;
        g_wc1T[t][q] = w_c1[q * F2n + t];
    } else if (idx < 3 * NA + 2 * NB) {
        int r = idx - 3 * NA - NB; int t = r / 80, q = r % 80;
        g_wb1T[t][q] = w_b1[q * F2n + t];
    }
}

// ---------------------------------------------------------------------------
// pre: packed-gate pre-activations. Coalesced weights via g_wihT*.
// ---------------------------------------------------------------------------
__global__ void pre_kernel(const float* __restrict__ x, int layer,
                           const float* __restrict__ bf, const float* __restrict__ bb)
{
    int s = blockIdx.x, b = blockIdx.y, d = blockIdx.z;
    int g = threadIdx.x;                       // 512 threads
    int in_dim = layer ? F2n : INn;
    const float* row = layer ? &g_out0[b][s][0] : (x + (b * Sn + s) * INn);
    const float* wT = layer ? &g_wihT1[d][0][0] : &g_wihT0[d][0][0];

    __shared__ float xs[F2n];
    for (int i = g; i < in_dim; i += blockDim.x) xs[i] = row[i];
    __syncthreads();

    float acc = (d ? bb : bf)[g];
    #pragma unroll 8
    for (int i = 0; i < in_dim; i++) acc += wT[i * G4 + g] * xs[i];

    int t = g & 127, gate = g >> 7;
    ((float*)&g_preP[d][b][s][t])[gate] = acc;
}

// ---------------------------------------------------------------------------
// LSTM scan: one CTA per (dir,b), 128 threads = one hidden unit each.
// Coalesced packed weights, double-buffered h, ONE barrier per step.
// ---------------------------------------------------------------------------
__global__ void __launch_bounds__(128, 1) scan_kernel(int layer)
{
    int d = blockIdx.x, b = blockIdx.y;
    int t = threadIdx.x;                       // 128
    __shared__ __align__(16) float4 hbuf4[2][Hn / 4];

    const float4* wP = &g_whhP[layer][d][0][0];
    float* out = layer ? &g_rnn[0][0][0] : &g_out0[0][0][0];

    float c = 0.f;
    ((float*)&hbuf4[0][0])[t] = 0.f;
    __syncthreads();

    for (int step = 0; step < Sn; step++) {
        int s = d ? (Sn - 1 - step) : step;
        int cur = step & 1, nxt = cur ^ 1;
        float4 acc = g_preP[d][b][s][t];

        #pragma unroll 8
        for (int k4 = 0; k4 < Hn / 4; k4++) {
            float4 hh = hbuf4[cur][k4];
            const float4* wp = wP + k4 * 4 * Hn + t;
            float4 w0 = wp[0];
            float4 w1 = wp[Hn];
            float4 w2 = wp[2 * Hn];
            float4 w3 = wp[3 * Hn];
            acc.x += w0.x * hh.x; acc.y += w0.y * hh.x; acc.z += w0.z * hh.x; acc.w += w0.w * hh.x;
            acc.x += w1.x * hh.y; acc.y += w1.y * hh.y; acc.z += w1.z * hh.y; acc.w += w1.w * hh.y;
            acc.x += w2.x * hh.z; acc.y += w2.y * hh.z; acc.z += w2.z * hh.z; acc.w += w2.w * hh.z;
            acc.x += w3.x * hh.w; acc.y += w3.y * hh.w; acc.z += w3.z * hh.w; acc.w += w3.w * hh.w;
        }

        float gi = sigf(acc.x), gf = sigf(acc.y);
        float gg = tanhf(acc.z), go = sigf(acc.w);
        c = gf * c + gi * gg;
        float h = go * tanhf(c);
        ((float*)&hbuf4[nxt][0])[t] = h;
        out[(b * Sn + s) * F2n + d * Hn + t] = h;
        __syncthreads();
    }
}

// ---------------------------------------------------------------------------
__global__ void cum_kernel()
{
    int b = blockIdx.x, t = threadIdx.x;       // 256 threads
    float acc = 0.f;
    for (int s = 0; s < Sn; s++) { acc += g_rnn[b][s][t]; g_cum[b][s][t] = acc; }
}

// ---------------------------------------------------------------------------
// Per-position u/v projections + cls/bin heads. Coalesced transposed weights.
// ---------------------------------------------------------------------------
__global__ void feat_kernel(const float* __restrict__ a_s0p,
                            const float* __restrict__ a_c0p, const float* __restrict__ b_c1,
                            const float* __restrict__ a_c1p, const float* __restrict__ w_c2,
                            const float* __restrict__ b_c2,
                            const float* __restrict__ a_b0p, const float* __restrict__ b_b1,
                            const float* __restrict__ a_b1p, const float* __restrict__ w_b2,
                            const float* __restrict__ b_b2,
                            float* __restrict__ out)
{
    int s = blockIdx.x, b = blockIdx.y, tid = threadIdx.x;   // 128 threads
    __shared__ float prs[F2n], prc[F2n], prb[F2n];
    __shared__ float hc[80], hb[80];
    float as0 = *a_s0p, ac0 = *a_c0p, ac1 = *a_c1p, ab0 = *a_b0p, ab1 = *a_b1p;

    for (int i = tid; i < F2n; i += 128) {
        float xv = g_rnn[b][s][i];
        prs[i] = xv >= 0.f ? xv : as0 * xv;
        prc[i] = xv >= 0.f ? xv : ac0 * xv;
        prb[i] = xv >= 0.f ? xv : ab0 * xv;
    }
    __syncthreads();

    if (tid < PHn) {
        float au = 0.f, av = 0.f;
        #pragma unroll 8
        for (int i = 0; i < F2n; i++) {
            float p = prs[i];
            au += g_w1dT[i][tid] * p;
            av += g_w1eT[i][tid] * p;
        }
        g_u[b][s][tid] = au;
        g_v[b][s][tid] = av;
    }
    if (tid < 80) {
        float a1 = b_c1[tid], a2 = b_b1[tid];
        #pragma unroll 8
        for (int i = 0; i < F2n; i++) {
            a1 += g_wc1T[i][tid] * prc[i];
            a2 += g_wb1T[i][tid] * prb[i];
        }
        hc[tid] = a1 >= 0.f ? a1 : ac1 * a1;
        hb[tid] = a2 >= 0.f ? a2 : ab1 * a2;
    }
    __syncthreads();
    if (tid < NCn) {
        float acc = b_c2[tid];
        const float* w = w_c2 + tid * 80;
        #pragma unroll 8
        for (int i = 0; i < 80; i++) acc += w[i] * hc[i];
        out[(b * Sn + s) * NCn + tid] = acc;
    }
    if (tid < 2) {
        float acc = b_b2[tid];
        const float* w = w_b2 + tid * 80;
        for (int i = 0; i < 80; i++) acc += w[i] * hb[i];
        out[Bn * Sn * NCn + (b * Sn + s) * 2 + tid] = acc;
    }
}

// ---------------------------------------------------------------------------
// Banded scores, one CTA per (b, i): all 64 window j's share the W1c pass.
// hidden[ph,j] = b_s1 + u[j] + v[i] + sum_t W1c[ph][t]*prelu(cum[i]-cum[j])[t]
// score[j]     = b_s2 + sum_ph w_s2[ph]*prelu(hidden)
// ---------------------------------------------------------------------------
__global__ void __launch_bounds__(128) sband_kernel(
        const float* __restrict__ a_s0p, const float* __restrict__ b_s1,
        const float* __restrict__ a_s1p, const float* __restrict__ w_s2,
        const float* __restrict__ b_s2)
{
    int i = blockIdx.x + 1, b = blockIdx.y, tid = threadIdx.x;  // 128 threads
    int start = i - Wn; if (start < 0) start = 0;

    __shared__ __align__(16) float pd[Wn * TP];   // 33792 B, [j][t-half]
    float acc[Wn];
    #pragma unroll
    for (int j = 0; j < Wn; j++) acc[j] = 0.f;

    float as0 = *a_s0p;

    for (int pass = 0; pass < 2; pass++) {
        int tb = pass * 128;
        float cI = g_cum[b][i][tb + tid];
        for (int j = 0; j < Wn; j++) {
            float dc = cI - g_cum[b][start + j][tb + tid];
            pd[j * TP + tid] = dc >= 0.f ? dc : as0 * dc;
        }
        __syncthreads();

        for (int t0 = 0; t0 < 128; t0 += 4) {
            float w0 = g_w1cT[tb + t0][tid];
            float w1 = g_w1cT[tb + t0 + 1][tid];
            float w2 = g_w1cT[tb + t0 + 2][tid];
            float w3 = g_w1cT[tb + t0 + 3][tid];
            #pragma unroll
            for (int j = 0; j < Wn; j++) {
                float4 p = *(const float4*)&pd[j * TP + t0];
                acc[j] += w0 * p.x + w1 * p.y + w2 * p.z + w3 * p.w;
            }
        }
        __syncthreads();
    }

    // epilogue: PReLU + w_s2 scale, reduce over ph
    float* red = pd;                              // alias (synced)
    float wsc  = tid < PHn ? w_s2[tid] : 0.f;
    float bs1v = tid < PHn ? b_s1[tid] : 0.f;
    float vi   = tid < PHn ? g_v[b][i][tid] : 0.f;
    float as1  = *a_s1p;

    for (int j = 0; j < Wn; j++) {
        if (tid < PHn) {
            float uj = g_u[b][start + j][tid];
            float hs = acc[j] + bs1v + uj + vi;
            float pr = hs >= 0.f ? hs : as1 * hs;
            red[j * 101 + tid] = pr * wsc;
        }
    }
    __syncthreads();
    if (tid < Wn) {
        float s = *b_s2;
        #pragma unroll 4
        for (int p = 0; p < PHn; p++) s += red[tid * 101 + p];
        g_sband[b][i][tid] = s;
    }
}

// ---------------------------------------------------------------------------
// DP + backtrack. Single CTA, 128 threads. Band prefetch; bp/edge-scores in smem.
// ---------------------------------------------------------------------------
__global__ void dp_kernel(const int* __restrict__ lengths, float* __restrict__ out)
{
    int tid = threadIdx.x;                     // 128
    __shared__ float best[Bn][Sn];
    __shared__ float esc[Bn][Sn];
    __shared__ int   bpS[Bn][Sn];
    __shared__ float wmax[4], wscr[4];
    __shared__ int   warg[4];

    for (int idx = tid; idx < Bn * Sn; idx += 128) ((float*)best)[idx] = 0.f;
    __syncthreads();

    int b = tid >> 6, k = tid & 63;
    int lane = tid & 31, wid = tid >> 5;

    float s_next = g_sband[b][1][k];
    for (int i = 1; i < Sn; i++) {
        float sc = s_next;
        if (i + 1 < Sn) s_next = g_sband[b][i + 1][k];
        int start = i - Wn; if (start < 0) start = 0;
        int j = start + k;
        bool valid = (j < i);
        float cv = valid ? best[b][j] + sc : -1e9f;
        float cs = sc;
        int   cj = j;
        #pragma unroll
        for (int off = 16; off; off >>= 1) {
            float ov = __shfl_down_sync(0xffffffffu, cv, off);
            int   oj = __shfl_down_sync(0xffffffffu, cj, off);
            float os = __shfl_down_sync(0xffffffffu, cs, off);
            if (ov > cv || (ov == cv && oj < cj)) { cv = ov; cj = oj; cs = os; }
        }
        if (lane == 0) { wmax[wid] = cv; warg[wid] = cj; wscr[wid] = cs; }
        __syncthreads();
        if (tid < Bn) {
            float v0 = wmax[tid * 2], v1 = wmax[tid * 2 + 1];
            int   j0 = warg[tid * 2], j1 = warg[tid * 2 + 1];
            float e0 = wscr[tid * 2], e1 = wscr[tid * 2 + 1];
            float mv; int mj; float me;
            if (v1 > v0 || (v1 == v0 && j1 < j0)) { mv = v1; mj = j1; me = e1; }
            else                                   { mv = v0; mj = j0; me = e0; }
            best[tid][i] = mv;
            bpS[tid][i]  = mj;
            esc[tid][i]  = me;
        }
        __syncthreads();
    }

    // ---- backtrack (all in smem) ----
    float* bm = out + Bn * Sn * NCn + Bn * Sn * 2;
    for (int idx = tid; idx < Bn * Sn; idx += 128) bm[idx] = 0.f;
    if (tid < Bn) { bpS[tid][0] = 0; esc[tid][0] = 0.f; }
    __syncthreads();
    if (tid < Bn) {
        int bb = tid;
        int cur = lengths[bb] - 1;
        float acc = 0.f;
        for (int st = 0; st < Sn; st++) {
            bm[bb * Sn + cur] = 1.0f;
            int prev = bpS[bb][cur];
            if (cur > 0) { acc += esc[bb][cur]; cur = prev; }
        }
        out[Bn * Sn * NCn + Bn * Sn * 2 + Bn * Sn + bb] = acc;
    }
}

// ---------------------------------------------------------------------------
extern "C" void kernel_launch(void* const* d_in, const int* in_sizes, int n_in,
                              void* d_out, int out_size)
{
    const float* x        = (const float*)d_in[0];
    const int*   lengths  = (const int*)  d_in[1];
    const float* w_ih_l0f = (const float*)d_in[2];
    const float* w_hh_l0f = (const float*)d_in[3];
    const float* b_l0f    = (const float*)d_in[4];
    const float* w_ih_l0b = (const float*)d_in[5];
    const float* w_hh_l0b = (const float*)d_in[6];
    const float* b_l0b    = (const float*)d_in[7];
    const float* w_ih_l1f = (const float*)d_in[8];
    const float* w_hh_l1f = (const float*)d_in[9];
    const float* b_l1f    = (const float*)d_in[10];
    const float* w_ih_l1b = (const float*)d_in[11];
    const float* w_hh_l1b = (const float*)d_in[12];
    const float* b_l1b    = (const float*)d_in[13];
    const float* a_s0     = (const float*)d_in[14];
    const float* w_s1     = (const float*)d_in[15];
    const float* b_s1     = (const float*)d_in[16];
    const float* a_s1     = (const float*)d_in[17];
    const float* w_s2     = (const float*)d_in[18];
    const float* b_s2     = (const float*)d_in[19];
    const float* a_c0     = (const float*)d_in[20];
    const float* w_c1     = (const float*)d_in[21];
    const float* b_c1     = (const float*)d_in[22];
    const float* a_c1     = (const float*)d_in[23];
    const float* w_c2     = (const float*)d_in[24];
    const float* b_c2     = (const float*)d_in[25];
    const float* a_b0     = (const float*)d_in[26];
    const float* w_b1     = (const float*)d_in[27];
    const float* b_b1     = (const float*)d_in[28];
    const float* a_b1     = (const float*)d_in[29];
    const float* w_b2     = (const float*)d_in[30];
    const float* b_b2     = (const float*)d_in[31];
    float* out = (float*)d_out;

    // weight prep (coalesced consumer layouts)
    prep_whh_kernel<<<dim3(Hn, 2, 2), Hn>>>(w_hh_l0f, w_hh_l0b, w_hh_l1f, w_hh_l1b);
    prep_wih_kernel<<<(2 * INn * G4 + 2 * F2n * G4 + 255) / 256, 256>>>(
        w_ih_l0f, w_ih_l0b, w_ih_l1f, w_ih_l1b);
    prep_score_kernel<<<(3 * F2n * 128 + 2 * F2n * 80 + 255) / 256, 256>>>(w_s1, w_c1, w_b1);

    // layer 0
    pre_kernel<<<dim3(Sn, Bn, 2), G4>>>(x, 0, b_l0f, b_l0b);
    scan_kernel<<<dim3(2, Bn), Hn>>>(0);
    // layer 1
    pre_kernel<<<dim3(Sn, Bn, 2), G4>>>(x, 1, b_l1f, b_l1b);
    scan_kernel<<<dim3(2, Bn), Hn>>>(1);

    // cumsum + per-position projections / heads
    cum_kernel<<<Bn, F2n>>>();
    feat_kernel<<<dim3(Sn, Bn), 128>>>(a_s0, a_c0, b_c1, a_c1, w_c2, b_c2,
                                       a_b0, b_b1, a_b1, w_b2, b_b2, out);
    // banded pair scores (one CTA per (b,i))
    sband_kernel<<<dim3(Sn - 1, Bn), 128>>>(a_s0, b_s1, a_s1, w_s2, b_s2);
    // DP + backtrack
    dp_kernel<<<1, 128>>>(lengths, out);
}

// round 5
// speedup vs baseline: 4.4253x; 1.0198x over previous
#include <cuda_runtime.h>
#include <math.h>
#include <stdint.h>

#define Bn  2
#define Sn  256
#define INn 80
#define Hn  128
#define G4  512
#define F2n 256
#define NCn 40
#define Wn  64
#define PHn 100
#define TP  132
#define CL  4      // scan cluster size (k-split / unit-split)

// ---------------- scratch (device globals) ---------------------------------
__device__ float4 g_whhP[2][2][Hn][Hn];    // [layer][dir][k][unit] = (Wi,Wf,Wg,Wo)[unit][k]
__device__ float  g_wihT0[2][INn][G4];     // [dir][i][g]
__device__ float  g_wihT1[2][F2n][G4];
__device__ float  g_w1cT[F2n][128];        // [t][ph], ph>=100 zero
__device__ float  g_w1dT[F2n][128];
__device__ float  g_w1eT[F2n][128];
__device__ float  g_wc1T[F2n][80];         // [t][q]
__device__ float  g_wb1T[F2n][80];
__device__ float4 g_preP[2][Bn][Sn][Hn];   // packed gates per unit
__device__ float  g_out0[Bn][Sn][F2n];
__device__ float  g_rnn [Bn][Sn][F2n];
__device__ float  g_cum [Bn][Sn][F2n];
__device__ float  g_u[Bn][Sn][PHn];
__device__ float  g_v[Bn][Sn][PHn];
__device__ float  g_sband[Bn][Sn][Wn];

__device__ __forceinline__ float sigf(float x) {
    return __fdividef(1.0f, 1.0f + __expf(-x));
}
__device__ __forceinline__ float tanh_fast(float x) {
    x = fminf(fmaxf(x, -15.0f), 15.0f);
    float e = __expf(2.0f * x);
    return __fdividef(e - 1.0f, e + 1.0f);
}

// ---- cluster / mbarrier helpers -------------------------------------------
__device__ __forceinline__ uint32_t smem_u32(const void* p) {
    uint32_t a;
    asm("{ .reg .u64 t; cvta.to.shared.u64 t, %1; cvt.u32.u64 %0, t; }" : "=r"(a) : "l"(p));
    return a;
}
__device__ __forceinline__ uint32_t mapa32(uint32_t a, uint32_t rank) {
    uint32_t r; asm("mapa.shared::cluster.u32 %0, %1, %2;" : "=r"(r) : "r"(a), "r"(rank));
    return r;
}
__device__ __forceinline__ void st_cl_f4(uint32_t a, float4 v) {
    asm volatile("st.shared::cluster.v4.f32 [%0], {%1,%2,%3,%4};"
                 :: "r"(a), "f"(v.x), "f"(v.y), "f"(v.z), "f"(v.w) : "memory");
}
__device__ __forceinline__ void mbar_init(uint32_t a, uint32_t count) {
    asm volatile("mbarrier.init.shared.b64 [%0], %1;" :: "r"(a), "r"(count) : "memory");
}
__device__ __forceinline__ void arrive_rel_cluster(uint32_t a) {
    asm volatile("mbarrier.arrive.release.cluster.shared::cluster.b64 _, [%0];"
                 :: "r"(a) : "memory");
}
__device__ __forceinline__ void wait_parity_acq_cluster(uint32_t a, uint32_t par) {
    uint32_t done;
    asm volatile("{\n\t.reg .pred p;\n\t"
                 "mbarrier.try_wait.parity.acquire.cluster.shared::cta.b64 p, [%1], %2, 0x989680;\n\t"
                 "selp.b32 %0,1,0,p;\n\t}"
                 : "=r"(done) : "r"(a), "r"(par) : "memory");
    while (!done) {
        asm volatile("{\n\t.reg .pred p;\n\t"
                     "mbarrier.try_wait.parity.acquire.cluster.shared::cta.b64 p, [%1], %2, 0x989680;\n\t"
                     "selp.b32 %0,1,0,p;\n\t}"
                     : "=r"(done) : "r"(a), "r"(par) : "memory");
    }
}
#define CLUSTER_SYNC_() do { \
    asm volatile("barrier.cluster.arrive.aligned;" ::: "memory"); \
    asm volatile("barrier.cluster.wait.aligned;" ::: "memory"); } while (0)

// ---------------------------------------------------------------------------
// Weight prep
// ---------------------------------------------------------------------------
__global__ void prep_whh_kernel(const float* __restrict__ w0f, const float* __restrict__ w0b,
                                const float* __restrict__ w1f, const float* __restrict__ w1b)
{
    int k = blockIdx.x, d = blockIdx.y, l = blockIdx.z, t = threadIdx.x;  // 128 thr
    const float* w = l ? (d ? w1b : w1f) : (d ? w0b : w0f);
    g_whhP[l][d][k][t] = make_float4(w[t * Hn + k], w[(Hn + t) * Hn + k],
                                     w[(2 * Hn + t) * Hn + k], w[(3 * Hn + t) * Hn + k]);
}

__global__ void prep_wih_kernel(const float* __restrict__ w0f, const float* __restrict__ w0b,
                                const float* __restrict__ w1f, const float* __restrict__ w1b)
{
    int idx = blockIdx.x * blockDim.x + threadIdx.x;
    const int N0 = 2 * INn * G4;
    const int N1 = 2 * F2n * G4;
    if (idx < N0) {
        int d = idx / (INn * G4), r = idx % (INn * G4);
        int i = r / G4, g = r % G4;
        g_wihT0[d][i][g] = (d ? w0b : w0f)[g * INn + i];
    } else if (idx < N0 + N1) {
        int r2 = idx - N0;
        int d = r2 / (F2n * G4), r = r2 % (F2n * G4);
        int i = r / G4, g = r % G4;
        g_wihT1[d][i][g] = (d ? w1b : w1f)[g * F2n + i];
    }
}

__global__ void prep_score_kernel(const float* __restrict__ w_s1,
                                  const float* __restrict__ w_c1,
                                  const float* __restrict__ w_b1)
{
    int idx = blockIdx.x * blockDim.x + threadIdx.x;
    const int NA = F2n * 128;
    const int NB = F2n * 80;
    if (idx < NA) {
        int t = idx >> 7, ph = idx & 127;
        g_w1cT[t][ph] = (ph < PHn) ? w_s1[ph * 768 + t] : 0.f;
    } else if (idx < 2 * NA) {
        int r = idx - NA; int t = r >> 7, ph = r & 127;
        g_w1dT[t][ph] = (ph < PHn) ? w_s1[ph * 768 + 256 + t] : 0.f;
    } else if (idx < 3 * NA) {
        int r = idx - 2 * NA; int t = r >> 7, ph = r & 127;
        g_w1eT[t][ph] = (ph < PHn) ? w_s1[ph * 768 + 512 + t] : 0.f;
    } else if (idx < 3 * NA + NB) {
        int r = idx - 3 * NA; int t = r / 80, q = r % 80;
        g_wc1T[t][q] = w_c1[q * F2n + t];
    } else if (idx < 3 * NA + 2 * NB) {
        int r = idx - 3 * NA - NB; int t = r / 80, q = r % 80;
        g_wb1T[t][q] = w_b1[q * F2n + t];
    }
}

// ---------------------------------------------------------------------------
// pre: packed-gate pre-activations
// ---------------------------------------------------------------------------
__global__ void pre_kernel(const float* __restrict__ x, int layer,
                           const float* __restrict__ bf, const float* __restrict__ bb)
{
    int s = blockIdx.x, b = blockIdx.y, d = blockIdx.z;
    int g = threadIdx.x;                       // 512 threads
    int in_dim = layer ? F2n : INn;
    const float* row = layer ? &g_out0[b][s][0] : (x + (b * Sn + s) * INn);
    const float* wT = layer ? &g_wihT1[d][0][0] : &g_wihT0[d][0][0];

    __shared__ float xs[F2n];
    for (int i = g; i < in_dim; i += blockDim.x) xs[i] = row[i];
    __syncthreads();

    float acc = (d ? bb : bf)[g];
    #pragma unroll 8
    for (int i = 0; i < in_dim; i++) acc += wT[i * G4 + g] * xs[i];

    int t = g & 127, gate = g >> 7;
    ((float*)&g_preP[d][b][s][t])[gate] = acc;
}

// ---------------------------------------------------------------------------
// LSTM scan: cluster of 4 CTAs per (layer,dir). CTA r owns hidden units
// [32r,32r+32) AND the k-slice [32r,32r+32) of all 512 gate rows, both
// batches. Only 4-gate partial sums are exchanged (DSMEM + mbarrier); the
// h values each CTA needs for its k-slice are exactly the ones it computes.
// 128 threads: thread t computes partial gates (i,f,g,o) of unit t over the
// k-slice for both batches.
// ---------------------------------------------------------------------------
__global__ void __cluster_dims__(CL, 1, 1) __launch_bounds__(128, 1)
scan_kernel(int layer)
{
    int r = blockIdx.x;          // cluster rank
    int d = blockIdx.y;          // direction
    int t = threadIdx.x;         // 0..127

    __shared__ __align__(16) float4 pbuf[2][CL][Bn][32];   // [stage][src][b][u_loc]
    __shared__ __align__(16) float  hbuf[2][64];           // [parity][k_loc*2 + b]
    __shared__ __align__(8)  unsigned long long mbar[2];

    uint32_t barL = smem_u32(&mbar[0]);
    if (t == 0) { mbar_init(barL, 128); mbar_init(barL + 8, 128); }
    if (t < 64) { hbuf[0][t] = 0.f; hbuf[1][t] = 0.f; }
    __syncthreads();
    CLUSTER_SYNC_();

    const float4* wp = &g_whhP[layer][d][r * 32][t];
    float* out = layer ? &g_rnn[0][0][0] : &g_out0[0][0][0];

    // writer side: destination CTA owns unit t
    int dest = t >> 5;
    int u_w  = t & 31;
    uint32_t pb_base = mapa32(smem_u32(&pbuf[0][r][0][u_w]), (uint32_t)dest);
    uint32_t barR    = mapa32(barL, (uint32_t)dest);
    const uint32_t STG = (uint32_t)sizeof(pbuf[0]);        // stage stride (bytes)
    const uint32_t BST = 32u * 16u;                        // b-plane stride

    // epilogue side (t < 64): b = t>>5, u_loc = t&31
    int eb = t >> 5, eu = t & 31;
    float cst = 0.f;

    for (int n = 0; n < Sn; n++) {
        int s  = d ? (Sn - 1 - n) : n;
        int hp = n & 1;
        int st = n & 1;
        uint32_t par = (uint32_t)((n >> 1) & 1);

        float i0 = 0.f, f0 = 0.f, g0 = 0.f, o0 = 0.f;
        float i1 = 0.f, f1 = 0.f, g1 = 0.f, o1 = 0.f;
        const float4* h4 = (const float4*)hbuf[hp];
        #pragma unroll 4
        for (int kk2 = 0; kk2 < 16; kk2++) {
            float4 hv = h4[kk2];
            float4 w0 = __ldg(wp + (2 * kk2) * Hn);
            float4 w1 = __ldg(wp + (2 * kk2 + 1) * Hn);
            i0 += w0.x * hv.x; f0 += w0.y * hv.x; g0 += w0.z * hv.x; o0 += w0.w * hv.x;
            i1 += w0.x * hv.y; f1 += w0.y * hv.y; g1 += w0.z * hv.y; o1 += w0.w * hv.y;
            i0 += w1.x * hv.z; f0 += w1.y * hv.z; g0 += w1.z * hv.z; o0 += w1.w * hv.z;
            i1 += w1.x * hv.w; f1 += w1.y * hv.w; g1 += w1.z * hv.w; o1 += w1.w * hv.w;
        }

        // ship partials to the unit owner (maybe self); release-ordered arrive
        uint32_t a0 = pb_base + (uint32_t)st * STG;
        st_cl_f4(a0,       make_float4(i0, f0, g0, o0));
        st_cl_f4(a0 + BST, make_float4(i1, f1, g1, o1));
        arrive_rel_cluster(barR + (uint32_t)st * 8u);

        if (t < 64) {
            wait_parity_acq_cluster(barL + (uint32_t)st * 8u, par);
            float4 g4 = g_preP[d][eb][s][r * 32 + eu];
            #pragma unroll
            for (int src = 0; src < CL; src++) {
                float4 pv = pbuf[st][src][eb][eu];
                g4.x += pv.x; g4.y += pv.y; g4.z += pv.z; g4.w += pv.w;
            }
            cst = sigf(g4.y) * cst + sigf(g4.x) * tanh_fast(g4.z);
            float h = sigf(g4.w) * tanh_fast(cst);
            hbuf[hp ^ 1][eu * 2 + eb] = h;
            out[(eb * Sn + s) * F2n + d * Hn + (r * 32 + eu)] = h;
        }
        __syncthreads();
    }
    CLUSTER_SYNC_();
}

// ---------------------------------------------------------------------------
__global__ void cum_kernel()
{
    int b = blockIdx.x, t = threadIdx.x;       // 256 threads
    float acc = 0.f;
    for (int s = 0; s < Sn; s++) { acc += g_rnn[b][s][t]; g_cum[b][s][t] = acc; }
}

// ---------------------------------------------------------------------------
// Per-position u/v projections + cls/bin heads
// ---------------------------------------------------------------------------
__global__ void feat_kernel(const float* __restrict__ a_s0p,
                            const float* __restrict__ a_c0p, const float* __restrict__ b_c1,
                            const float* __restrict__ a_c1p, const float* __restrict__ w_c2,
                            const float* __restrict__ b_c2,
                            const float* __restrict__ a_b0p, const float* __restrict__ b_b1,
                            const float* __restrict__ a_b1p, const float* __restrict__ w_b2,
                            const float* __restrict__ b_b2,
                            float* __restrict__ out)
{
    int s = blockIdx.x, b = blockIdx.y, tid = threadIdx.x;   // 128 threads
    __shared__ float prs[F2n], prc[F2n], prb[F2n];
    __shared__ float hc[80], hb[80];
    float as0 = *a_s0p, ac0 = *a_c0p, ac1 = *a_c1p, ab0 = *a_b0p, ab1 = *a_b1p;

    for (int i = tid; i < F2n; i += 128) {
        float xv = g_rnn[b][s][i];
        prs[i] = xv >= 0.f ? xv : as0 * xv;
        prc[i] = xv >= 0.f ? xv : ac0 * xv;
        prb[i] = xv >= 0.f ? xv : ab0 * xv;
    }
    __syncthreads();

    if (tid < PHn) {
        float au = 0.f, av = 0.f;
        #pragma unroll 8
        for (int i = 0; i < F2n; i++) {
            float p = prs[i];
            au += g_w1dT[i][tid] * p;
            av += g_w1eT[i][tid] * p;
        }
        g_u[b][s][tid] = au;
        g_v[b][s][tid] = av;
    }
    if (tid < 80) {
        float a1 = b_c1[tid], a2 = b_b1[tid];
        #pragma unroll 8
        for (int i = 0; i < F2n; i++) {
            a1 += g_wc1T[i][tid] * prc[i];
            a2 += g_wb1T[i][tid] * prb[i];
        }
        hc[tid] = a1 >= 0.f ? a1 : ac1 * a1;
        hb[tid] = a2 >= 0.f ? a2 : ab1 * a2;
    }
    __syncthreads();
    if (tid < NCn) {
        float acc = b_c2[tid];
        const float* w = w_c2 + tid * 80;
        #pragma unroll 8
        for (int i = 0; i < 80; i++) acc += w[i] * hc[i];
        out[(b * Sn + s) * NCn + tid] = acc;
    }
    if (tid < 2) {
        float acc = b_b2[tid];
        const float* w = w_b2 + tid * 80;
        for (int i = 0; i < 80; i++) acc += w[i] * hb[i];
        out[Bn * Sn * NCn + (b * Sn + s) * 2 + tid] = acc;
    }
}

// ---------------------------------------------------------------------------
// Banded scores, one CTA per (b, i)
// ---------------------------------------------------------------------------
__global__ void __launch_bounds__(128) sband_kernel(
        const float* __restrict__ a_s0p, const float* __restrict__ b_s1,
        const float* __restrict__ a_s1p, const float* __restrict__ w_s2,
        const float* __restrict__ b_s2)
{
    int i = blockIdx.x + 1, b = blockIdx.y, tid = threadIdx.x;  // 128 threads
    int start = i - Wn; if (start < 0) start = 0;

    __shared__ __align__(16) float pd[Wn * TP];
    float acc[Wn];
    #pragma unroll
    for (int j = 0; j < Wn; j++) acc[j] = 0.f;

    float as0 = *a_s0p;

    for (int pass = 0; pass < 2; pass++) {
        int tb = pass * 128;
        float cI = g_cum[b][i][tb + tid];
        for (int j = 0; j < Wn; j++) {
            float dc = cI - g_cum[b][start + j][tb + tid];
            pd[j * TP + tid] = dc >= 0.f ? dc : as0 * dc;
        }
        __syncthreads();

        for (int t0 = 0; t0 < 128; t0 += 4) {
            float w0 = g_w1cT[tb + t0][tid];
            float w1 = g_w1cT[tb + t0 + 1][tid];
            float w2 = g_w1cT[tb + t0 + 2][tid];
            float w3 = g_w1cT[tb + t0 + 3][tid];
            #pragma unroll
            for (int j = 0; j < Wn; j++) {
                float4 p = *(const float4*)&pd[j * TP + t0];
                acc[j] += w0 * p.x + w1 * p.y + w2 * p.z + w3 * p.w;
            }
        }
        __syncthreads();
    }

    float* red = pd;
    float wsc  = tid < PHn ? w_s2[tid] : 0.f;
    float bs1v = tid < PHn ? b_s1[tid] : 0.f;
    float vi   = tid < PHn ? g_v[b][i][tid] : 0.f;
    float as1  = *a_s1p;

    for (int j = 0; j < Wn; j++) {
        if (tid < PHn) {
            float uj = g_u[b][start + j][tid];
            float hs = acc[j] + bs1v + uj + vi;
            float pr = hs >= 0.f ? hs : as1 * hs;
            red[j * 101 + tid] = pr * wsc;
        }
    }
    __syncthreads();
    if (tid < Wn) {
        float s = *b_s2;
        #pragma unroll 4
        for (int p = 0; p < PHn; p++) s += red[tid * 101 + p];
        g_sband[b][i][tid] = s;
    }
}

// ---------------------------------------------------------------------------
// DP + backtrack: one warp per batch, no __syncthreads in the hot loop.
// Candidate key packs (ordered-float(value) << 32) | (~j): max key = max
// value with first-occurrence (min j) tie-break, matching jnp.argmax.
// ---------------------------------------------------------------------------
__global__ void dp_kernel(const int* __restrict__ lengths, float* __restrict__ out)
{
    int tid = threadIdx.x;                     // 64 threads = 2 warps
    int b = tid >> 5, lane = tid & 31;
    __shared__ float best[Bn][Sn];
    __shared__ float esc[Bn][Sn];
    __shared__ int   bpS[Bn][Sn];

    for (int idx = tid; idx < Bn * Sn; idx += 64) ((float*)best)[idx] = 0.f;
    __syncthreads();

    float sa  = g_sband[b][1][lane];
    float sb2 = g_sband[b][1][lane + 32];
    for (int i = 1; i < Sn; i++) {
        float s0 = sa, s1 = sb2;
        if (i + 1 < Sn) { sa = g_sband[b][i + 1][lane]; sb2 = g_sband[b][i + 1][lane + 32]; }
        int start = i - Wn; if (start < 0) start = 0;
        int j0 = start + lane, j1 = start + lane + 32;
        unsigned long long key = 0ull;
        float v0 = 0.f, v1 = 0.f;
        if (j0 < i) {
            v0 = best[b][j0] + s0;
            unsigned u = __float_as_uint(v0);
            u = (u & 0x80000000u) ? ~u : (u | 0x80000000u);
            key = ((unsigned long long)u << 32) | (unsigned)(0xFFFFFFFFu - (unsigned)j0);
        }
        if (j1 < i) {
            v1 = best[b][j1] + s1;
            unsigned u = __float_as_uint(v1);
            u = (u & 0x80000000u) ? ~u : (u | 0x80000000u);
            unsigned long long k1 = ((unsigned long long)u << 32) | (unsigned)(0xFFFFFFFFu - (unsigned)j1);
            if (k1 > key) key = k1;
        }
        #pragma unroll
        for (int off = 16; off; off >>= 1) {
            unsigned long long ok = __shfl_down_sync(0xffffffffu, key, off);
            if (ok > key) key = ok;
        }
        key = __shfl_sync(0xffffffffu, key, 0);
        int jstar = (int)(0xFFFFFFFFu - (unsigned)(key & 0xFFFFFFFFull));
        if (j0 == jstar && j0 < i) { best[b][i] = v0; bpS[b][i] = jstar; esc[b][i] = s0; }
        if (j1 == jstar && j1 < i) { best[b][i] = v1; bpS[b][i] = jstar; esc[b][i] = s1; }
        __syncwarp();
    }
    __syncthreads();

    // ---- backtrack ----
    float* bm = out + Bn * Sn * NCn + Bn * Sn * 2;
    for (int idx = tid; idx < Bn * Sn; idx += 64) bm[idx] = 0.f;
    if (tid < Bn) { bpS[tid][0] = 0; esc[tid][0] = 0.f; }
    __syncthreads();
    if (lane == 0) {
        int cur = lengths[b] - 1;
        float acc = 0.f;
        for (int st2 = 0; st2 < Sn; st2++) {
            bm[b * Sn + cur] = 1.0f;
            int prev = bpS[b][cur];
            if (cur > 0) { acc += esc[b][cur]; cur = prev; }
        }
        out[Bn * Sn * NCn + Bn * Sn * 2 + Bn * Sn + b] = acc;
    }
}

// ---------------------------------------------------------------------------
extern "C" void kernel_launch(void* const* d_in, const int* in_sizes, int n_in,
                              void* d_out, int out_size)
{
    const float* x        = (const float*)d_in[0];
    const int*   lengths  = (const int*)  d_in[1];
    const float* w_ih_l0f = (const float*)d_in[2];
    const float* w_hh_l0f = (const float*)d_in[3];
    const float* b_l0f    = (const float*)d_in[4];
    const float* w_ih_l0b = (const float*)d_in[5];
    const float* w_hh_l0b = (const float*)d_in[6];
    const float* b_l0b    = (const float*)d_in[7];
    const float* w_ih_l1f = (const float*)d_in[8];
    const float* w_hh_l1f = (const float*)d_in[9];
    const float* b_l1f    = (const float*)d_in[10];
    const float* w_ih_l1b = (const float*)d_in[11];
    const float* w_hh_l1b = (const float*)d_in[12];
    const float* b_l1b    = (const float*)d_in[13];
    const float* a_s0     = (const float*)d_in[14];
    const float* w_s1     = (const float*)d_in[15];
    const float* b_s1     = (const float*)d_in[16];
    const float* a_s1     = (const float*)d_in[17];
    const float* w_s2     = (const float*)d_in[18];
    const float* b_s2     = (const float*)d_in[19];
    const float* a_c0     = (const float*)d_in[20];
    const float* w_c1     = (const float*)d_in[21];
    const float* b_c1     = (const float*)d_in[22];
    const float* a_c1     = (const float*)d_in[23];
    const float* w_c2     = (const float*)d_in[24];
    const float* b_c2     = (const float*)d_in[25];
    const float* a_b0     = (const float*)d_in[26];
    const float* w_b1     = (const float*)d_in[27];
    const float* b_b1     = (const float*)d_in[28];
    const float* a_b1     = (const float*)d_in[29];
    const float* w_b2     = (const float*)d_in[30];
    const float* b_b2     = (const float*)d_in[31];
    float* out = (float*)d_out;

    // launches ordered so that ncu (-s 5 -c 1) captures scan_kernel(layer 1)
    prep_whh_kernel<<<dim3(Hn, 2, 2), Hn>>>(w_hh_l0f, w_hh_l0b, w_hh_l1f, w_hh_l1b);   // 1
    prep_wih_kernel<<<(2 * INn * G4 + 2 * F2n * G4 + 255) / 256, 256>>>(
        w_ih_l0f, w_ih_l0b, w_ih_l1f, w_ih_l1b);                                       // 2
    pre_kernel<<<dim3(Sn, Bn, 2), G4>>>(x, 0, b_l0f, b_l0b);                           // 3
    scan_kernel<<<dim3(CL, 2), 128>>>(0);                                              // 4
    pre_kernel<<<dim3(Sn, Bn, 2), G4>>>(x, 1, b_l1f, b_l1b);                           // 5
    scan_kernel<<<dim3(CL, 2), 128>>>(1);                                              // 6 <- profiled
    prep_score_kernel<<<(3 * F2n * 128 + 2 * F2n * 80 + 255) / 256, 256>>>(w_s1, w_c1, w_b1); // 7
    cum_kernel<<<Bn, F2n>>>();                                                         // 8
    feat_kernel<<<dim3(Sn, Bn), 128>>>(a_s0, a_c0, b_c1, a_c1, w_c2, b_c2,
                                       a_b0, b_b1, a_b1, w_b2, b_b2, out);             // 9
    sband_kernel<<<dim3(Sn - 1, Bn), 128>>>(a_s0, b_s1, a_s1, w_s2, b_s2);             // 10
    dp_kernel<<<1, 64>>>(lengths, out);                                                // 11
}

// round 6
// speedup vs baseline: 4.7221x; 1.0671x over previous
#include <cuda_runtime.h>
#include <math.h>
#include <stdint.h>

#define Bn  2
#define Sn  256
#define INn 80
#define Hn  128
#define G4  512
#define F2n 256
#define NCn 40
#define Wn  64
#define PHn 100
#define TP  132
#define CL  4      // scan cluster size (k-split / unit-split)

// ---------------- scratch (device globals) ---------------------------------
__device__ float4 g_whhP[2][2][Hn][Hn];    // [layer][dir][k][unit] = (Wi,Wf,Wg,Wo)[unit][k]
__device__ float  g_wihT0[2][INn][G4];     // [dir][i][g]
__device__ float  g_wihT1[2][F2n][G4];
__device__ float  g_w1cT[F2n][128];        // [t][ph], ph>=100 zero
__device__ float  g_w1dT[F2n][128];
__device__ float  g_w1eT[F2n][128];
__device__ float  g_wc1T[F2n][80];         // [t][q]
__device__ float  g_wb1T[F2n][80];
__device__ float4 g_preP[2][Bn][Sn][Hn];   // packed gates per unit
__device__ float  g_out0[Bn][Sn][F2n];
__device__ float  g_rnn [Bn][Sn][F2n];
__device__ float  g_cum [Bn][Sn][F2n];
__device__ float  g_u[Bn][Sn][PHn];
__device__ float  g_v[Bn][Sn][PHn];
__device__ float  g_sband[Bn][Sn][Wn];

__device__ __forceinline__ float sigf(float x) {
    return __fdividef(1.0f, 1.0f + __expf(-x));
}
__device__ __forceinline__ float tanh_fast(float x) {
    x = fminf(fmaxf(x, -15.0f), 15.0f);
    float e = __expf(2.0f * x);
    return __fdividef(e - 1.0f, e + 1.0f);
}

// ---- cluster / mbarrier helpers -------------------------------------------
__device__ __forceinline__ uint32_t smem_u32(const void* p) {
    uint32_t a;
    asm("{ .reg .u64 t; cvta.to.shared.u64 t, %1; cvt.u32.u64 %0, t; }" : "=r"(a) : "l"(p));
    return a;
}
__device__ __forceinline__ uint32_t mapa32(uint32_t a, uint32_t rank) {
    uint32_t r; asm("mapa.shared::cluster.u32 %0, %1, %2;" : "=r"(r) : "r"(a), "r"(rank));
    return r;
}
__device__ __forceinline__ void st_cl_f4(uint32_t a, float4 v) {
    asm volatile("st.shared::cluster.v4.f32 [%0], {%1,%2,%3,%4};"
                 :: "r"(a), "f"(v.x), "f"(v.y), "f"(v.z), "f"(v.w) : "memory");
}
__device__ __forceinline__ void mbar_init(uint32_t a, uint32_t count) {
    asm volatile("mbarrier.init.shared.b64 [%0], %1;" :: "r"(a), "r"(count) : "memory");
}
__device__ __forceinline__ void arrive_rel_cluster(uint32_t a) {
    asm volatile("mbarrier.arrive.release.cluster.shared::cluster.b64 _, [%0];"
                 :: "r"(a) : "memory");
}
__device__ __forceinline__ void wait_parity_acq_cluster(uint32_t a, uint32_t par) {
    uint32_t done;
    asm volatile("{\n\t.reg .pred p;\n\t"
                 "mbarrier.try_wait.parity.acquire.cluster.shared::cta.b64 p, [%1], %2, 0x989680;\n\t"
                 "selp.b32 %0,1,0,p;\n\t}"
                 : "=r"(done) : "r"(a), "r"(par) : "memory");
    while (!done) {
        asm volatile("{\n\t.reg .pred p;\n\t"
                     "mbarrier.try_wait.parity.acquire.cluster.shared::cta.b64 p, [%1], %2, 0x989680;\n\t"
                     "selp.b32 %0,1,0,p;\n\t}"
                     : "=r"(done) : "r"(a), "r"(par) : "memory");
    }
}
#define CLUSTER_SYNC_() do { \
    asm volatile("barrier.cluster.arrive.aligned;" ::: "memory"); \
    asm volatile("barrier.cluster.wait.aligned;" ::: "memory"); } while (0)

// ---------------------------------------------------------------------------
// Weight prep
// ---------------------------------------------------------------------------
__global__ void prep_whh_kernel(const float* __restrict__ w0f, const float* __restrict__ w0b,
                                const float* __restrict__ w1f, const float* __restrict__ w1b)
{
    int k = blockIdx.x, d = blockIdx.y, l = blockIdx.z, t = threadIdx.x;  // 128 thr
    const float* w = l ? (d ? w1b : w1f) : (d ? w0b : w0f);
    g_whhP[l][d][k][t] = make_float4(w[t * Hn + k], w[(Hn + t) * Hn + k],
                                     w[(2 * Hn + t) * Hn + k], w[(3 * Hn + t) * Hn + k]);
}

__global__ void prep_wih_kernel(const float* __restrict__ w0f, const float* __restrict__ w0b,
                                const float* __restrict__ w1f, const float* __restrict__ w1b)
{
    int idx = blockIdx.x * blockDim.x + threadIdx.x;
    const int N0 = 2 * INn * G4;
    const int N1 = 2 * F2n * G4;
    if (idx < N0) {
        int d = idx / (INn * G4), r = idx % (INn * G4);
        int i = r / G4, g = r % G4;
        g_wihT0[d][i][g] = (d ? w0b : w0f)[g * INn + i];
    } else if (idx < N0 + N1) {
        int r2 = idx - N0;
        int d = r2 / (F2n * G4), r = r2 % (F2n * G4);
        int i = r / G4, g = r % G4;
        g_wihT1[d][i][g] = (d ? w1b : w1f)[g * F2n + i];
    }
}

__global__ void prep_score_kernel(const float* __restrict__ w_s1,
                                  const float* __restrict__ w_c1,
                                  const float* __restrict__ w_b1)
{
    int idx = blockIdx.x * blockDim.x + threadIdx.x;
    const int NA = F2n * 128;
    const int NB = F2n * 80;
    if (idx < NA) {
        int t = idx >> 7, ph = idx & 127;
        g_w1cT[t][ph] = (ph < PHn) ? w_s1[ph * 768 + t] : 0.f;
    } else if (idx < 2 * NA) {
        int r = idx - NA; int t = r >> 7, ph = r & 127;
        g_w1dT[t][ph] = (ph < PHn) ? w_s1[ph * 768 + 256 + t] : 0.f;
    } else if (idx < 3 * NA) {
        int r = idx - 2 * NA; int t = r >> 7, ph = r & 127;
        g_w1eT[t][ph] = (ph < PHn) ? w_s1[ph * 768 + 512 + t] : 0.f;
    } else if (idx < 3 * NA + NB) {
        int r = idx - 3 * NA; int t = r / 80, q = r % 80;
        g_wc1T[t][q] = w_c1[q * F2n + t];
    } else if (idx < 3 * NA + 2 * NB) {
        int r = idx - 3 * NA - NB; int t = r / 80, q = r % 80;
        g_wb1T[t][q] = w_b1[q * F2n + t];
    }
}

// ---------------------------------------------------------------------------
// pre: packed-gate pre-activations
// ---------------------------------------------------------------------------
__global__ void pre_kernel(const float* __restrict__ x, int layer,
                           const float* __restrict__ bf, const float* __restrict__ bb)
{
    int s = blockIdx.x, b = blockIdx.y, d = blockIdx.z;
    int g = threadIdx.x;                       // 512 threads
    int in_dim = layer ? F2n : INn;
    const float* row = layer ? &g_out0[b][s][0] : (x + (b * Sn + s) * INn);
    const float* wT = layer ? &g_wihT1[d][0][0] : &g_wihT0[d][0][0];

    __shared__ float xs[F2n];
    for (int i = g; i < in_dim; i += blockDim.x) xs[i] = row[i];
    __syncthreads();

    float acc = (d ? bb : bf)[g];
    #pragma unroll 8
    for (int i = 0; i < in_dim; i++) acc += wT[i * G4 + g] * xs[i];

    int t = g & 127, gate = g >> 7;
    ((float*)&g_preP[d][b][s][t])[gate] = acc;
}

// ---------------------------------------------------------------------------
// LSTM scan: cluster of 4 CTAs per (layer,dir). CTA r owns hidden units
// [32r,32r+32) AND k-slice [32r,32r+32) of all gate rows, both batches.
// Per step: weak cluster stores of 4-gate partials -> __syncthreads ->
// ONE release-arrive per destination CTA (threads 0..3) -> acquire-wait ->
// epilogue. Next-step g_preP prefetched under the barrier wait.
// ---------------------------------------------------------------------------
__global__ void __cluster_dims__(CL, 1, 1) __launch_bounds__(128, 1)
scan_kernel(int layer)
{
    int r = blockIdx.x;          // cluster rank
    int d = blockIdx.y;          // direction
    int t = threadIdx.x;         // 0..127

    __shared__ __align__(16) float4 pbuf[2][CL][Bn][32];   // [stage][src][b][u_loc]
    __shared__ __align__(16) float  hbuf[2][64];           // [parity][k_loc*2 + b]
    __shared__ __align__(8)  unsigned long long mbar[2];

    uint32_t barL = smem_u32(&mbar[0]);
    if (t == 0) { mbar_init(barL, CL); mbar_init(barL + 8, CL); }
    if (t < 64) { hbuf[0][t] = 0.f; hbuf[1][t] = 0.f; }
    __syncthreads();
    CLUSTER_SYNC_();

    const float4* wp = &g_whhP[layer][d][r * 32][t];
    float* out = layer ? &g_rnn[0][0][0] : &g_out0[0][0][0];

    // writer side: destination CTA owns unit t
    int dest = t >> 5;
    int u_w  = t & 31;
    uint32_t pb_base = mapa32(smem_u32(&pbuf[0][r][0][u_w]), (uint32_t)dest);
    uint32_t barArr  = (t < CL) ? mapa32(barL, (uint32_t)t) : 0u;
    const uint32_t STG = (uint32_t)sizeof(pbuf[0]);        // stage stride (bytes)
    const uint32_t BST = 32u * 16u;                        // b-plane stride

    // epilogue side (t < 64): b = t>>5, u_loc = t&31
    int eb = t >> 5, eu = t & 31;
    float cst = 0.f;
    float4 pre_cur = make_float4(0.f, 0.f, 0.f, 0.f);
    if (t < 64) {
        int sf = d ? (Sn - 1) : 0;
        pre_cur = g_preP[d][eb][sf][r * 32 + eu];
    }

    for (int n = 0; n < Sn; n++) {
        int s  = d ? (Sn - 1 - n) : n;
        int hp = n & 1;
        int st = n & 1;
        uint32_t par = (uint32_t)((n >> 1) & 1);

        float i0 = 0.f, f0 = 0.f, g0 = 0.f, o0 = 0.f;
        float i1 = 0.f, f1 = 0.f, g1 = 0.f, o1 = 0.f;
        const float4* h4 = (const float4*)hbuf[hp];
        #pragma unroll 4
        for (int kk2 = 0; kk2 < 16; kk2++) {
            float4 hv = h4[kk2];
            float4 w0 = __ldg(wp + (2 * kk2) * Hn);
            float4 w1 = __ldg(wp + (2 * kk2 + 1) * Hn);
            i0 += w0.x * hv.x; f0 += w0.y * hv.x; g0 += w0.z * hv.x; o0 += w0.w * hv.x;
            i1 += w0.x * hv.y; f1 += w0.y * hv.y; g1 += w0.z * hv.y; o1 += w0.w * hv.y;
            i0 += w1.x * hv.z; f0 += w1.y * hv.z; g0 += w1.z * hv.z; o0 += w1.w * hv.z;
            i1 += w1.x * hv.w; f1 += w1.y * hv.w; g1 += w1.z * hv.w; o1 += w1.w * hv.w;
        }

        // weak cluster stores of partials (maybe to self)
        uint32_t a0 = pb_base + (uint32_t)st * STG;
        st_cl_f4(a0,       make_float4(i0, f0, g0, o0));
        st_cl_f4(a0 + BST, make_float4(i1, f1, g1, o1));

        // make all threads' stores visible-before the elected release-arrives
        __syncthreads();
        if (t < CL) arrive_rel_cluster(barArr + (uint32_t)st * 8u);

        // prefetch next step's pre-activations under the barrier wait
        float4 pre_nxt = make_float4(0.f, 0.f, 0.f, 0.f);
        if (t < 64 && n + 1 < Sn) {
            int sn = d ? (Sn - 2 - n) : (n + 1);
            pre_nxt = g_preP[d][eb][sn][r * 32 + eu];
        }

        if (t < 64) {
            wait_parity_acq_cluster(barL + (uint32_t)st * 8u, par);
            float4 g4 = pre_cur;
            #pragma unroll
            for (int src = 0; src < CL; src++) {
                float4 pv = pbuf[st][src][eb][eu];
                g4.x += pv.x; g4.y += pv.y; g4.z += pv.z; g4.w += pv.w;
            }
            cst = sigf(g4.y) * cst + sigf(g4.x) * tanh_fast(g4.z);
            float h = sigf(g4.w) * tanh_fast(cst);
            hbuf[hp ^ 1][eu * 2 + eb] = h;
            out[(eb * Sn + s) * F2n + d * Hn + (r * 32 + eu)] = h;
            pre_cur = pre_nxt;
        }
        __syncthreads();
    }
    CLUSTER_SYNC_();
}

// ---------------------------------------------------------------------------
__global__ void cum_kernel()
{
    int b = blockIdx.x, t = threadIdx.x;       // 256 threads
    float acc = 0.f;
    for (int s = 0; s < Sn; s++) { acc += g_rnn[b][s][t]; g_cum[b][s][t] = acc; }
}

// ---------------------------------------------------------------------------
// Per-position u/v projections + cls/bin heads
// ---------------------------------------------------------------------------
__global__ void feat_kernel(const float* __restrict__ a_s0p,
                            const float* __restrict__ a_c0p, const float* __restrict__ b_c1,
                            const float* __restrict__ a_c1p, const float* __restrict__ w_c2,
                            const float* __restrict__ b_c2,
                            const float* __restrict__ a_b0p, const float* __restrict__ b_b1,
                            const float* __restrict__ a_b1p, const float* __restrict__ w_b2,
                            const float* __restrict__ b_b2,
                            float* __restrict__ out)
{
    int s = blockIdx.x, b = blockIdx.y, tid = threadIdx.x;   // 128 threads
    __shared__ float prs[F2n], prc[F2n], prb[F2n];
    __shared__ float hc[80], hb[80];
    float as0 = *a_s0p, ac0 = *a_c0p, ac1 = *a_c1p, ab0 = *a_b0p, ab1 = *a_b1p;

    for (int i = tid; i < F2n; i += 128) {
        float xv = g_rnn[b][s][i];
        prs[i] = xv >= 0.f ? xv : as0 * xv;
        prc[i] = xv >= 0.f ? xv : ac0 * xv;
        prb[i] = xv >= 0.f ? xv : ab0 * xv;
    }
    __syncthreads();

    if (tid < PHn) {
        float au = 0.f, av = 0.f;
        #pragma unroll 8
        for (int i = 0; i < F2n; i++) {
            float p = prs[i];
            au += g_w1dT[i][tid] * p;
            av += g_w1eT[i][tid] * p;
        }
        g_u[b][s][tid] = au;
        g_v[b][s][tid] = av;
    }
    if (tid < 80) {
        float a1 = b_c1[tid], a2 = b_b1[tid];
        #pragma unroll 8
        for (int i = 0; i < F2n; i++) {
            a1 += g_wc1T[i][tid] * prc[i];
            a2 += g_wb1T[i][tid] * prb[i];
        }
        hc[tid] = a1 >= 0.f ? a1 : ac1 * a1;
        hb[tid] = a2 >= 0.f ? a2 : ab1 * a2;
    }
    __syncthreads();
    if (tid < NCn) {
        float acc = b_c2[tid];
        const float* w = w_c2 + tid * 80;
        #pragma unroll 8
        for (int i = 0; i < 80; i++) acc += w[i] * hc[i];
        out[(b * Sn + s) * NCn + tid] = acc;
    }
    if (tid < 2) {
        float acc = b_b2[tid];
        const float* w = w_b2 + tid * 80;
        for (int i = 0; i < 80; i++) acc += w[i] * hb[i];
        out[Bn * Sn * NCn + (b * Sn + s) * 2 + tid] = acc;
    }
}

// ---------------------------------------------------------------------------
// Banded scores, one CTA per (b, i)
// ---------------------------------------------------------------------------
__global__ void __launch_bounds__(128) sband_kernel(
        const float* __restrict__ a_s0p, const float* __restrict__ b_s1,
        const float* __restrict__ a_s1p, const float* __restrict__ w_s2,
        const float* __restrict__ b_s2)
{
    int i = blockIdx.x + 1, b = blockIdx.y, tid = threadIdx.x;  // 128 threads
    int start = i - Wn; if (start < 0) start = 0;

    __shared__ __align__(16) float pd[Wn * TP];
    float acc[Wn];
    #pragma unroll
    for (int j = 0; j < Wn; j++) acc[j] = 0.f;

    float as0 = *a_s0p;

    for (int pass = 0; pass < 2; pass++) {
        int tb = pass * 128;
        float cI = g_cum[b][i][tb + tid];
        for (int j = 0; j < Wn; j++) {
            float dc = cI - g_cum[b][start + j][tb + tid];
            pd[j * TP + tid] = dc >= 0.f ? dc : as0 * dc;
        }
        __syncthreads();

        for (int t0 = 0; t0 < 128; t0 += 4) {
            float w0 = g_w1cT[tb + t0][tid];
            float w1 = g_w1cT[tb + t0 + 1][tid];
            float w2 = g_w1cT[tb + t0 + 2][tid];
            float w3 = g_w1cT[tb + t0 + 3][tid];
            #pragma unroll
            for (int j = 0; j < Wn; j++) {
                float4 p = *(const float4*)&pd[j * TP + t0];
                acc[j] += w0 * p.x + w1 * p.y + w2 * p.z + w3 * p.w;
            }
        }
        __syncthreads();
    }

    float* red = pd;
    float wsc  = tid < PHn ? w_s2[tid] : 0.f;
    float bs1v = tid < PHn ? b_s1[tid] : 0.f;
    float vi   = tid < PHn ? g_v[b][i][tid] : 0.f;
    float as1  = *a_s1p;

    for (int j = 0; j < Wn; j++) {
        if (tid < PHn) {
            float uj = g_u[b][start + j][tid];
            float hs = acc[j] + bs1v + uj + vi;
            float pr = hs >= 0.f ? hs : as1 * hs;
            red[j * 101 + tid] = pr * wsc;
        }
    }
    __syncthreads();
    if (tid < Wn) {
        float s = *b_s2;
        #pragma unroll 4
        for (int p = 0; p < PHn; p++) s += red[tid * 101 + p];
        g_sband[b][i][tid] = s;
    }
}

// ---------------------------------------------------------------------------
// DP + backtrack: one warp per batch, no __syncthreads in the hot loop.
// ---------------------------------------------------------------------------
__global__ void dp_kernel(const int* __restrict__ lengths, float* __restrict__ out)
{
    int tid = threadIdx.x;                     // 64 threads = 2 warps
    int b = tid >> 5, lane = tid & 31;
    __shared__ float best[Bn][Sn];
    __shared__ float esc[Bn][Sn];
    __shared__ int   bpS[Bn][Sn];

    for (int idx = tid; idx < Bn * Sn; idx += 64) ((float*)best)[idx] = 0.f;
    __syncthreads();

    float sa  = g_sband[b][1][lane];
    float sb2 = g_sband[b][1][lane + 32];
    for (int i = 1; i < Sn; i++) {
        float s0 = sa, s1 = sb2;
        if (i + 1 < Sn) { sa = g_sband[b][i + 1][lane]; sb2 = g_sband[b][i + 1][lane + 32]; }
        int start = i - Wn; if (start < 0) start = 0;
        int j0 = start + lane, j1 = start + lane + 32;
        unsigned long long key = 0ull;
        float v0 = 0.f, v1 = 0.f;
        if (j0 < i) {
            v0 = best[b][j0] + s0;
            unsigned u = __float_as_uint(v0);
            u = (u & 0x80000000u) ? ~u : (u | 0x80000000u);
            key = ((unsigned long long)u << 32) | (unsigned)(0xFFFFFFFFu - (unsigned)j0);
        }
        if (j1 < i) {
            v1 = best[b][j1] + s1;
            unsigned u = __float_as_uint(v1);
            u = (u & 0x80000000u) ? ~u : (u | 0x80000000u);
            unsigned long long k1 = ((unsigned long long)u << 32) | (unsigned)(0xFFFFFFFFu - (unsigned)j1);
            if (k1 > key) key = k1;
        }
        #pragma unroll
        for (int off = 16; off; off >>= 1) {
            unsigned long long ok = __shfl_down_sync(0xffffffffu, key, off);
            if (ok > key) key = ok;
        }
        key = __shfl_sync(0xffffffffu, key, 0);
        int jstar = (int)(0xFFFFFFFFu - (unsigned)(key & 0xFFFFFFFFull));
        if (j0 == jstar && j0 < i) { best[b][i] = v0; bpS[b][i] = jstar; esc[b][i] = s0; }
        if (j1 == jstar && j1 < i) { best[b][i] = v1; bpS[b][i] = jstar; esc[b][i] = s1; }
        __syncwarp();
    }
    __syncthreads();

    // ---- backtrack ----
    float* bm = out + Bn * Sn * NCn + Bn * Sn * 2;
    for (int idx = tid; idx < Bn * Sn; idx += 64) bm[idx] = 0.f;
    if (tid < Bn) { bpS[tid][0] = 0; esc[tid][0] = 0.f; }
    __syncthreads();
    if (lane == 0) {
        int cur = lengths[b] - 1;
        float acc = 0.f;
        for (int st2 = 0; st2 < Sn; st2++) {
            bm[b * Sn + cur] = 1.0f;
            int prev = bpS[b][cur];
            if (cur > 0) { acc += esc[b][cur]; cur = prev; }
        }
        out[Bn * Sn * NCn + Bn * Sn * 2 + Bn * Sn + b] = acc;
    }
}

// ---------------------------------------------------------------------------
extern "C" void kernel_launch(void* const* d_in, const int* in_sizes, int n_in,
                              void* d_out, int out_size)
{
    const float* x        = (const float*)d_in[0];
    const int*   lengths  = (const int*)  d_in[1];
    const float* w_ih_l0f = (const float*)d_in[2];
    const float* w_hh_l0f = (const float*)d_in[3];
    const float* b_l0f    = (const float*)d_in[4];
    const float* w_ih_l0b = (const float*)d_in[5];
    const float* w_hh_l0b = (const float*)d_in[6];
    const float* b_l0b    = (const float*)d_in[7];
    const float* w_ih_l1f = (const float*)d_in[8];
    const float* w_hh_l1f = (const float*)d_in[9];
    const float* b_l1f    = (const float*)d_in[10];
    const float* w_ih_l1b = (const float*)d_in[11];
    const float* w_hh_l1b = (const float*)d_in[12];
    const float* b_l1b    = (const float*)d_in[13];
    const float* a_s0     = (const float*)d_in[14];
    const float* w_s1     = (const float*)d_in[15];
    const float* b_s1     = (const float*)d_in[16];
    const float* a_s1     = (const float*)d_in[17];
    const float* w_s2     = (const float*)d_in[18];
    const float* b_s2     = (const float*)d_in[19];
    const float* a_c0     = (const float*)d_in[20];
    const float* w_c1     = (const float*)d_in[21];
    const float* b_c1     = (const float*)d_in[22];
    const float* a_c1     = (const float*)d_in[23];
    const float* w_c2     = (const float*)d_in[24];
    const float* b_c2     = (const float*)d_in[25];
    const float* a_b0     = (const float*)d_in[26];
    const float* w_b1     = (const float*)d_in[27];
    const float* b_b1     = (const float*)d_in[28];
    const float* a_b1     = (const float*)d_in[29];
    const float* w_b2     = (const float*)d_in[30];
    const float* b_b2     = (const float*)d_in[31];
    float* out = (float*)d_out;

    // launches ordered so that ncu (-s 5 -c 1) captures scan_kernel(layer 1)
    prep_whh_kernel<<<dim3(Hn, 2, 2), Hn>>>(w_hh_l0f, w_hh_l0b, w_hh_l1f, w_hh_l1b);   // 1
    prep_wih_kernel<<<(2 * INn * G4 + 2 * F2n * G4 + 255) / 256, 256>>>(
        w_ih_l0f, w_ih_l0b, w_ih_l1f, w_ih_l1b);                                       // 2
    pre_kernel<<<dim3(Sn, Bn, 2), G4>>>(x, 0, b_l0f, b_l0b);                           // 3
    scan_kernel<<<dim3(CL, 2), 128>>>(0);                                              // 4
    pre_kernel<<<dim3(Sn, Bn, 2), G4>>>(x, 1, b_l1f, b_l1b);                           // 5
    scan_kernel<<<dim3(CL, 2), 128>>>(1);                                              // 6 <- profiled
    prep_score_kernel<<<(3 * F2n * 128 + 2 * F2n * 80 + 255) / 256, 256>>>(w_s1, w_c1, w_b1); // 7
    cum_kernel<<<Bn, F2n>>>();                                                         // 8
    feat_kernel<<<dim3(Sn, Bn), 128>>>(a_s0, a_c0, b_c1, a_c1, w_c2, b_c2,
                                       a_b0, b_b1, a_b1, w_b2, b_b2, out);             // 9
    sband_kernel<<<dim3(Sn - 1, Bn), 128>>>(a_s0, b_s1, a_s1, w_s2, b_s2);             // 10
    dp_kernel<<<1, 64>>>(lengths, out);                                                // 11
}

// round 9
// speedup vs baseline: 6.5383x; 1.3846x over previous
#include <cuda_runtime.h>
#include <math.h>
#include <stdint.h>

#define Bn  2
#define Sn  256
#define INn 80
#define Hn  128
#define G4  512
#define F2n 256
#define NCn 40
#define Wn  64
#define PHn 100
#define TP  132
#define CL  4      // scan cluster size (unit-split, k replicated)

// ---------------- scratch (device globals) ---------------------------------
__device__ float  g_wihT0[2][INn][G4];     // [dir][i][g]
__device__ float  g_wihT1[2][F2n][G4];
__device__ float  g_w1cT[F2n][128];        // [t][ph], ph>=100 zero
__device__ float  g_w1dT[F2n][128];
__device__ float  g_w1eT[F2n][128];
__device__ float  g_wc1T[F2n][80];         // [t][q]
__device__ float  g_wb1T[F2n][80];
__device__ float  g_preG[2][Bn][Sn][G4];   // gate pre-activations, row = gate*128+unit
__device__ float  g_out0[Bn][Sn][F2n];
__device__ float  g_rnn [Bn][Sn][F2n];
__device__ float  g_cum [Bn][Sn][F2n];
__device__ float  g_u[Bn][Sn][PHn];
__device__ float  g_v[Bn][Sn][PHn];
__device__ float  g_sband[Bn][Sn][Wn];

__device__ __forceinline__ float sigf(float x) {
    return __fdividef(1.0f, 1.0f + __expf(-x));
}
__device__ __forceinline__ float tanh_fast(float x) {
    x = fminf(fmaxf(x, -15.0f), 15.0f);
    float e = __expf(2.0f * x);
    return __fdividef(e - 1.0f, e + 1.0f);
}

// ---- cluster / mbarrier helpers -------------------------------------------
__device__ __forceinline__ uint32_t smem_u32(const void* p) {
    uint32_t a;
    asm("{ .reg .u64 t; cvta.to.shared.u64 t, %1; cvt.u32.u64 %0, t; }" : "=r"(a) : "l"(p));
    return a;
}
__device__ __forceinline__ uint32_t mapa32(uint32_t a, uint32_t rank) {
    uint32_t r; asm("mapa.shared::cluster.u32 %0, %1, %2;" : "=r"(r) : "r"(a), "r"(rank));
    return r;
}
__device__ __forceinline__ void st_cl_f32(uint32_t a, float v) {
    asm volatile("st.shared::cluster.f32 [%0], %1;" :: "r"(a), "f"(v) : "memory");
}
__device__ __forceinline__ void mbar_init(uint32_t a, uint32_t count) {
    asm volatile("mbarrier.init.shared.b64 [%0], %1;" :: "r"(a), "r"(count) : "memory");
}
__device__ __forceinline__ void arrive_rel_cluster(uint32_t a) {
    asm volatile("mbarrier.arrive.release.cluster.shared::cluster.b64 _, [%0];"
                 :: "r"(a) : "memory");
}
__device__ __forceinline__ void wait_parity_acq_cluster(uint32_t a, uint32_t par) {
    uint32_t done;
    asm volatile("{\n\t.reg .pred p;\n\t"
                 "mbarrier.try_wait.parity.acquire.cluster.shared::cta.b64 p, [%1], %2, 0x989680;\n\t"
                 "selp.b32 %0,1,0,p;\n\t}"
                 : "=r"(done) : "r"(a), "r"(par) : "memory");
    while (!done) {
        asm volatile("{\n\t.reg .pred p;\n\t"
                     "mbarrier.try_wait.parity.acquire.cluster.shared::cta.b64 p, [%1], %2, 0x989680;\n\t"
                     "selp.b32 %0,1,0,p;\n\t}"
                     : "=r"(done) : "r"(a), "r"(par) : "memory");
    }
}
#define CLUSTER_SYNC_() do { \
    asm volatile("barrier.cluster.arrive.aligned;" ::: "memory"); \
    asm volatile("barrier.cluster.wait.aligned;" ::: "memory"); } while (0)

// ---------------------------------------------------------------------------
// Weight prep (wih transpose + score-MLP transposes; whh now read directly)
// ---------------------------------------------------------------------------
__global__ void prep_wih_kernel(const float* __restrict__ w0f, const float* __restrict__ w0b,
                                const float* __restrict__ w1f, const float* __restrict__ w1b)
{
    int idx = blockIdx.x * blockDim.x + threadIdx.x;
    const int N0 = 2 * INn * G4;
    const int N1 = 2 * F2n * G4;
    if (idx < N0) {
        int d = idx / (INn * G4), r = idx % (INn * G4);
        int i = r / G4, g = r % G4;
        g_wihT0[d][i][g] = (d ? w0b : w0f)[g * INn + i];
    } else if (idx < N0 + N1) {
        int r2 = idx - N0;
        int d = r2 / (F2n * G4), r = r2 % (F2n * G4);
        int i = r / G4, g = r % G4;
        g_wihT1[d][i][g] = (d ? w1b : w1f)[g * F2n + i];
    }
}

__global__ void prep_score_kernel(const float* __restrict__ w_s1,
                                  const float* __restrict__ w_c1,
                                  const float* __restrict__ w_b1)
{
    int idx = blockIdx.x * blockDim.x + threadIdx.x;
    const int NA = F2n * 128;
    const int NB = F2n * 80;
    if (idx < NA) {
        int t = idx >> 7, ph = idx & 127;
        g_w1cT[t][ph] = (ph < PHn) ? w_s1[ph * 768 + t] : 0.f;
    } else if (idx < 2 * NA) {
        int r = idx - NA; int t = r >> 7, ph = r & 127;
        g_w1dT[t][ph] = (ph < PHn) ? w_s1[ph * 768 + 256 + t] : 0.f;
    } else if (idx < 3 * NA) {
        int r = idx - 2 * NA; int t = r >> 7, ph = r & 127;
        g_w1eT[t][ph] = (ph < PHn) ? w_s1[ph * 768 + 512 + t] : 0.f;
    } else if (idx < 3 * NA + NB) {
        int r = idx - 3 * NA; int t = r / 80, q = r % 80;
        g_wc1T[t][q] = w_c1[q * F2n + t];
    } else if (idx < 3 * NA + 2 * NB) {
        int r = idx - 3 * NA - NB; int t = r / 80, q = r % 80;
        g_wb1T[t][q] = w_b1[q * F2n + t];
    }
}

// ---------------------------------------------------------------------------
// pre: gate pre-activations, scalar layout row = gate*128+unit (coalesced for scan)
// ---------------------------------------------------------------------------
__global__ void pre_kernel(const float* __restrict__ x, int layer,
                           const float* __restrict__ bf, const float* __restrict__ bb)
{
    int s = blockIdx.x, b = blockIdx.y, d = blockIdx.z;
    int g = threadIdx.x;                       // 512 threads; g = gate*128+unit
    int in_dim = layer ? F2n : INn;
    const float* row = layer ? &g_out0[b][s][0] : (x + (b * Sn + s) * INn);
    const float* wT = layer ? &g_wihT1[d][0][0] : &g_wihT0[d][0][0];

    __shared__ float xs[F2n];
    for (int i = g; i < in_dim; i += blockDim.x) xs[i] = row[i];
    __syncthreads();

    float acc = (d ? bb : bf)[g];
    #pragma unroll 8
    for (int i = 0; i < in_dim; i++) acc += wT[i * G4 + g] * xs[i];

    g_preG[d][b][s][g] = acc;
}

// ---------------------------------------------------------------------------
// LSTM scan: cluster of 4 CTAs per (layer,dir); CTA r owns units [32r,32r+32)
// with FULL k range. Weights live in REGISTERS (64 floats/thread, loaded once).
// 256 threads: t -> (kh = t>>7, row = t&127), row = gate*32 + u.
// Per step: compute half-k gate partials for both batches (h broadcast in smem),
// CTA-local reduce + c/h update, then broadcast own 32 h's x2 batches to all
// ranks (256B via DSMEM) + one elected release-arrive per destination CTA.
// ---------------------------------------------------------------------------
__global__ void __cluster_dims__(CL, 1, 1) __launch_bounds__(256, 1)
scan_kernel(int layer, const float* __restrict__ whhF, const float* __restrict__ whhB)
{
    int r = blockIdx.x;           // cluster rank (unit group)
    int d = blockIdx.y;           // direction
    int t = threadIdx.x;          // 0..255
    int row = t & 127;            // gate*32 + u
    int kh  = t >> 7;             // k half
    int gate = row >> 5, u = row & 31;

    __shared__ __align__(16) float hbuf[2][Bn][Hn];   // [parity][b][k]
    __shared__ float pall[Bn][2][128];                // [b][kh][row]
    __shared__ __align__(8) unsigned long long mbar[2];

    uint32_t barL = smem_u32(&mbar[0]);
    if (t == 0) { mbar_init(barL, CL); mbar_init(barL + 8, CL); }
    for (int idx = t; idx < Bn * Hn; idx += 256) ((float*)hbuf[0])[idx] = 0.f;

    // load this thread's weight row half into registers (once)
    const float* whh = d ? whhB : whhF;
    const float4* wsrc = (const float4*)(whh + (gate * Hn + r * 32 + u) * Hn + kh * 64);
    float4 w[16];
    #pragma unroll
    for (int q = 0; q < 16; q++) w[q] = wsrc[q];

    __syncthreads();
    CLUSTER_SYNC_();

    float* out = layer ? &g_rnn[0][0][0] : &g_out0[0][0][0];
    const float* preB = &g_preG[d][0][0][0];          // [b][s][512]
    int prow = gate * Hn + r * 32 + u;
    float pm = kh ? 0.f : 1.f;                        // only kh==0 carries pre

    // epilogue mapping (t<64): eb = t>>5, eu = t&31
    int eb = t >> 5, eu = t & 31;
    float cst = 0.f;
    uint32_t hA = smem_u32(&hbuf[0][eb][r * 32 + eu]);
    uint32_t hD0 = mapa32(hA, 0), hD1 = mapa32(hA, 1),
             hD2 = mapa32(hA, 2), hD3 = mapa32(hA, 3);
    uint32_t barArr = (t < CL) ? mapa32(barL, (uint32_t)t) : 0u;
    const uint32_t HST = (uint32_t)(Bn * Hn * sizeof(float));   // parity stride

    unsigned wp0 = 0, wp1 = 0;

    int sf = d ? (Sn - 1) : 0;
    float pr0 = preB[(0 * Sn + sf) * G4 + prow] * pm;
    float pr1 = preB[(1 * Sn + sf) * G4 + prow] * pm;

    for (int n = 0; n < Sn; n++) {
        int p = n & 1;
        if (n) {
            if (p) { wait_parity_acq_cluster(barL + 8, wp1); wp1 ^= 1; }
            else   { wait_parity_acq_cluster(barL,     wp0); wp0 ^= 1; }
        }
        int s = d ? (Sn - 1 - n) : n;

        const float4* h0 = (const float4*)&hbuf[p][0][kh * 64];
        const float4* h1 = (const float4*)&hbuf[p][1][kh * 64];
        float a0 = pr0, a1 = pr1;
        #pragma unroll
        for (int q = 0; q < 16; q++) {
            float4 wq = w[q];
            float4 v0 = h0[q], v1 = h1[q];
            a0 += wq.x * v0.x + wq.y * v0.y + wq.z * v0.z + wq.w * v0.w;
            a1 += wq.x * v1.x + wq.y * v1.y + wq.z * v1.z + wq.w * v1.w;
        }
        pall[0][kh][row] = a0;
        pall[1][kh][row] = a1;
        __syncthreads();

        // prefetch next step's pre under the epilogue/communication
        if (n + 1 < Sn) {
            int sn = d ? (Sn - 2 - n) : (n + 1);
            pr0 = preB[(0 * Sn + sn) * G4 + prow] * pm;
            pr1 = preB[(1 * Sn + sn) * G4 + prow] * pm;
        }

        if (t < 64) {
            float gi = pall[eb][0][eu]      + pall[eb][1][eu];
            float gf = pall[eb][0][32 + eu] + pall[eb][1][32 + eu];
            float gg = pall[eb][0][64 + eu] + pall[eb][1][64 + eu];
            float go = pall[eb][0][96 + eu] + pall[eb][1][96 + eu];
            cst = sigf(gf) * cst + sigf(gi) * tanh_fast(gg);
            float h = sigf(go) * tanh_fast(cst);
            out[(eb * Sn + s) * F2n + d * Hn + (r * 32 + eu)] = h;
            uint32_t off = (uint32_t)(p ^ 1) * HST;
            st_cl_f32(hD0 + off, h);
            st_cl_f32(hD1 + off, h);
            st_cl_f32(hD2 + off, h);
            st_cl_f32(hD3 + off, h);
        }
        __syncthreads();
        if (t < CL) arrive_rel_cluster(barArr + (uint32_t)(p ^ 1) * 8u);
    }
    CLUSTER_SYNC_();
}

// ---------------------------------------------------------------------------
__global__ void cum_kernel()
{
    int b = blockIdx.x, t = threadIdx.x;       // 256 threads
    float acc = 0.f;
    for (int s = 0; s < Sn; s++) { acc += g_rnn[b][s][t]; g_cum[b][s][t] = acc; }
}

// ---------------------------------------------------------------------------
// Per-position u/v projections + cls/bin heads
// ---------------------------------------------------------------------------
__global__ void feat_kernel(const float* __restrict__ a_s0p,
                            const float* __restrict__ a_c0p, const float* __restrict__ b_c1,
                            const float* __restrict__ a_c1p, const float* __restrict__ w_c2,
                            const float* __restrict__ b_c2,
                            const float* __restrict__ a_b0p, const float* __restrict__ b_b1,
                            const float* __restrict__ a_b1p, const float* __restrict__ w_b2,
                            const float* __restrict__ b_b2,
                            float* __restrict__ out)
{
    int s = blockIdx.x, b = blockIdx.y, tid = threadIdx.x;   // 128 threads
    __shared__ float prs[F2n], prc[F2n], prb[F2n];
    __shared__ float hc[80], hb[80];
    float as0 = *a_s0p, ac0 = *a_c0p, ac1 = *a_c1p, ab0 = *a_b0p, ab1 = *a_b1p;

    for (int i = tid; i < F2n; i += 128) {
        float xv = g_rnn[b][s][i];
        prs[i] = xv >= 0.f ? xv : as0 * xv;
        prc[i] = xv >= 0.f ? xv : ac0 * xv;
        prb[i] = xv >= 0.f ? xv : ab0 * xv;
    }
    __syncthreads();

    if (tid < PHn) {
        float au = 0.f, av = 0.f;
        #pragma unroll 8
        for (int i = 0; i < F2n; i++) {
            float p = prs[i];
            au += g_w1dT[i][tid] * p;
            av += g_w1eT[i][tid] * p;
        }
        g_u[b][s][tid] = au;
        g_v[b][s][tid] = av;
    }
    if (tid < 80) {
        float a1 = b_c1[tid], a2 = b_b1[tid];
        #pragma unroll 8
        for (int i = 0; i < F2n; i++) {
            a1 += g_wc1T[i][tid] * prc[i];
            a2 += g_wb1T[i][tid] * prb[i];
        }
        hc[tid] = a1 >= 0.f ? a1 : ac1 * a1;
        hb[tid] = a2 >= 0.f ? a2 : ab1 * a2;
    }
    __syncthreads();
    if (tid < NCn) {
        float acc = b_c2[tid];
        const float* w = w_c2 + tid * 80;
        #pragma unroll 8
        for (int i = 0; i < 80; i++) acc += w[i] * hc[i];
        out[(b * Sn + s) * NCn + tid] = acc;
    }
    if (tid < 2) {
        float acc = b_b2[tid];
        const float* w = w_b2 + tid * 80;
        for (int i = 0; i < 80; i++) acc += w[i] * hb[i];
        out[Bn * Sn * NCn + (b * Sn + s) * 2 + tid] = acc;
    }
}

// ---------------------------------------------------------------------------
// Banded scores, one CTA per (b, i)
// ---------------------------------------------------------------------------
__global__ void __launch_bounds__(128) sband_kernel(
        const float* __restrict__ a_s0p, const float* __restrict__ b_s1,
        const float* __restrict__ a_s1p, const float* __restrict__ w_s2,
        const float* __restrict__ b_s2)
{
    int i = blockIdx.x + 1, b = blockIdx.y, tid = threadIdx.x;  // 128 threads
    int start = i - Wn; if (start < 0) start = 0;

    __shared__ __align__(16) float pd[Wn * TP];
    float acc[Wn];
    #pragma unroll
    for (int j = 0; j < Wn; j++) acc[j] = 0.f;

    float as0 = *a_s0p;

    for (int pass = 0; pass < 2; pass++) {
        int tb = pass * 128;
        float cI = g_cum[b][i][tb + tid];
        for (int j = 0; j < Wn; j++) {
            float dc = cI - g_cum[b][start + j][tb + tid];
            pd[j * TP + tid] = dc >= 0.f ? dc : as0 * dc;
        }
        __syncthreads();

        for (int t0 = 0; t0 < 128; t0 += 4) {
            float w0 = g_w1cT[tb + t0][tid];
            float w1 = g_w1cT[tb + t0 + 1][tid];
            float w2 = g_w1cT[tb + t0 + 2][tid];
            float w3 = g_w1cT[tb + t0 + 3][tid];
            #pragma unroll
            for (int j = 0; j < Wn; j++) {
                float4 p = *(const float4*)&pd[j * TP + t0];
                acc[j] += w0 * p.x + w1 * p.y + w2 * p.z + w3 * p.w;
            }
        }
        __syncthreads();
    }

    float* red = pd;
    float wsc  = tid < PHn ? w_s2[tid] : 0.f;
    float bs1v = tid < PHn ? b_s1[tid] : 0.f;
    float vi   = tid < PHn ? g_v[b][i][tid] : 0.f;
    float as1  = *a_s1p;

    for (int j = 0; j < Wn; j++) {
        if (tid < PHn) {
            float uj = g_u[b][start + j][tid];
            float hs = acc[j] + bs1v + uj + vi;
            float pr = hs >= 0.f ? hs : as1 * hs;
            red[j * 101 + tid] = pr * wsc;
        }
    }
    __syncthreads();
    if (tid < Wn) {
        float s = *b_s2;
        #pragma unroll 4
        for (int p = 0; p < PHn; p++) s += red[tid * 101 + p];
        g_sband[b][i][tid] = s;
    }
}

// ---------------------------------------------------------------------------
// DP + backtrack: one warp per batch, no __syncthreads in the hot loop.
// ---------------------------------------------------------------------------
__global__ void dp_kernel(const int* __restrict__ lengths, float* __restrict__ out)
{
    int tid = threadIdx.x;                     // 64 threads = 2 warps
    int b = tid >> 5, lane = tid & 31;
    __shared__ float best[Bn][Sn];
    __shared__ float esc[Bn][Sn];
    __shared__ int   bpS[Bn][Sn];

    for (int idx = tid; idx < Bn * Sn; idx += 64) ((float*)best)[idx] = 0.f;
    __syncthreads();

    float sa  = g_sband[b][1][lane];
    float sb2 = g_sband[b][1][lane + 32];
    for (int i = 1; i < Sn; i++) {
        float s0 = sa, s1 = sb2;
        if (i + 1 < Sn) { sa = g_sband[b][i + 1][lane]; sb2 = g_sband[b][i + 1][lane + 32]; }
        int start = i - Wn; if (start < 0) start = 0;
        int j0 = start + lane, j1 = start + lane + 32;
        unsigned long long key = 0ull;
        float v0 = 0.f, v1 = 0.f;
        if (j0 < i) {
            v0 = best[b][j0] + s0;
            unsigned u = __float_as_uint(v0);
            u = (u & 0x80000000u) ? ~u : (u | 0x80000000u);
            key = ((unsigned long long)u << 32) | (unsigned)(0xFFFFFFFFu - (unsigned)j0);
        }
        if (j1 < i) {
            v1 = best[b][j1] + s1;
            unsigned u = __float_as_uint(v1);
            u = (u & 0x80000000u) ? ~u : (u | 0x80000000u);
            unsigned long long k1 = ((unsigned long long)u << 32) | (unsigned)(0xFFFFFFFFu - (unsigned)j1);
            if (k1 > key) key = k1;
        }
        #pragma unroll
        for (int off = 16; off; off >>= 1) {
            unsigned long long ok = __shfl_down_sync(0xffffffffu, key, off);
            if (ok > key) key = ok;
        }
        key = __shfl_sync(0xffffffffu, key, 0);
        int jstar = (int)(0xFFFFFFFFu - (unsigned)(key & 0xFFFFFFFFull));
        if (j0 == jstar && j0 < i) { best[b][i] = v0; bpS[b][i] = jstar; esc[b][i] = s0; }
        if (j1 == jstar && j1 < i) { best[b][i] = v1; bpS[b][i] = jstar; esc[b][i] = s1; }
        __syncwarp();
    }
    __syncthreads();

    // ---- backtrack ----
    float* bm = out + Bn * Sn * NCn + Bn * Sn * 2;
    for (int idx = tid; idx < Bn * Sn; idx += 64) bm[idx] = 0.f;
    if (tid < Bn) { bpS[tid][0] = 0; esc[tid][0] = 0.f; }
    __syncthreads();
    if (lane == 0) {
        int cur = lengths[b] - 1;
        float acc = 0.f;
        for (int st2 = 0; st2 < Sn; st2++) {
            bm[b * Sn + cur] = 1.0f;
            int prev = bpS[b][cur];
            if (cur > 0) { acc += esc[b][cur]; cur = prev; }
        }
        out[Bn * Sn * NCn + Bn * Sn * 2 + Bn * Sn + b] = acc;
    }
}

// ---------------------------------------------------------------------------
extern "C" void kernel_launch(void* const* d_in, const int* in_sizes, int n_in,
                              void* d_out, int out_size)
{
    const float* x        = (const float*)d_in[0];
    const int*   lengths  = (const int*)  d_in[1];
    const float* w_ih_l0f = (const float*)d_in[2];
    const float* w_hh_l0f = (const float*)d_in[3];
    const float* b_l0f    = (const float*)d_in[4];
    const float* w_ih_l0b = (const float*)d_in[5];
    const float* w_hh_l0b = (const float*)d_in[6];
    const float* b_l0b    = (const float*)d_in[7];
    const float* w_ih_l1f = (const float*)d_in[8];
    const float* w_hh_l1f = (const float*)d_in[9];
    const float* b_l1f    = (const float*)d_in[10];
    const float* w_ih_l1b = (const float*)d_in[11];
    const float* w_hh_l1b = (const float*)d_in[12];
    const float* b_l1b    = (const float*)d_in[13];
    const float* a_s0     = (const float*)d_in[14];
    const float* w_s1     = (const float*)d_in[15];
    const float* b_s1     = (const float*)d_in[16];
    const float* a_s1     = (const float*)d_in[17];
    const float* w_s2     = (const float*)d_in[18];
    const float* b_s2     = (const float*)d_in[19];
    const float* a_c0     = (const float*)d_in[20];
    const float* w_c1     = (const float*)d_in[21];
    const float* b_c1     = (const float*)d_in[22];
    const float* a_c1     = (const float*)d_in[23];
    const float* w_c2     = (const float*)d_in[24];
    const float* b_c2     = (const float*)d_in[25];
    const float* a_b0     = (const float*)d_in[26];
    const float* w_b1     = (const float*)d_in[27];
    const float* b_b1     = (const float*)d_in[28];
    const float* a_b1     = (const float*)d_in[29];
    const float* w_b2     = (const float*)d_in[30];
    const float* b_b2     = (const float*)d_in[31];
    float* out = (float*)d_out;

    // launches ordered so that ncu (-s 5 -c 1) captures scan_kernel(layer 1)
    prep_wih_kernel<<<(2 * INn * G4 + 2 * F2n * G4 + 255) / 256, 256>>>(
        w_ih_l0f, w_ih_l0b, w_ih_l1f, w_ih_l1b);                                       // 1
    pre_kernel<<<dim3(Sn, Bn, 2), G4>>>(x, 0, b_l0f, b_l0b);                           // 2
    scan_kernel<<<dim3(CL, 2), 256>>>(0, w_hh_l0f, w_hh_l0b);                          // 3
    pre_kernel<<<dim3(Sn, Bn, 2), G4>>>(x, 1, b_l1f, b_l1b);                           // 4
    prep_score_kernel<<<(3 * F2n * 128 + 2 * F2n * 80 + 255) / 256, 256>>>(w_s1, w_c1, w_b1); // 5
    scan_kernel<<<dim3(CL, 2), 256>>>(1, w_hh_l1f, w_hh_l1b);                          // 6 <- profiled
    cum_kernel<<<Bn, F2n>>>();                                                         // 7
    feat_kernel<<<dim3(Sn, Bn), 128>>>(a_s0, a_c0, b_c1, a_c1, w_c2, b_c2,
                                       a_b0, b_b1, a_b1, w_b2, b_b2, out);             // 8
    sband_kernel<<<dim3(Sn - 1, Bn), 128>>>(a_s0, b_s1, a_s1, w_s2, b_s2);             // 9
    dp_kernel<<<1, 64>>>(lengths, out);                                                // 10
}

// round 10
// speedup vs baseline: 8.1443x; 1.2456x over previous
#include <cuda_runtime.h>
#include <math.h>
#include <stdint.h>

#define Bn  2
#define Sn  256
#define INn 80
#define Hn  128
#define G4  512
#define F2n 256
#define NCn 40
#define Wn  64
#define PHn 100
#define TP  132
#define CL  4      // scan cluster size (unit-split, k replicated)

// ---------------- scratch (device globals) ---------------------------------
__device__ float  g_wihT0[2][INn][G4];     // [dir][i][g]
__device__ float  g_wihT1[2][F2n][G4];
__device__ float  g_w1cT[F2n][128];        // [t][ph], ph>=100 zero
__device__ float  g_w1dT[F2n][128];
__device__ float  g_w1eT[F2n][128];
__device__ float  g_wc1T[F2n][80];         // [t][q]
__device__ float  g_wb1T[F2n][80];
__device__ float  g_preG[2][Bn][Sn][G4];   // gate pre-activations, row = gate*128+unit
__device__ float  g_out0[Bn][Sn][F2n];
__device__ float  g_rnn [Bn][Sn][F2n];
__device__ float  g_cum [Bn][Sn][F2n];
__device__ float  g_u[Bn][Sn][PHn];
__device__ float  g_v[Bn][Sn][PHn];
__device__ float  g_sband[Bn][Sn][Wn];

__device__ __forceinline__ float sigf(float x) {
    return __fdividef(1.0f, 1.0f + __expf(-x));
}
__device__ __forceinline__ float tanh_fast(float x) {
    x = fminf(fmaxf(x, -15.0f), 15.0f);
    float e = __expf(2.0f * x);
    return __fdividef(e - 1.0f, e + 1.0f);
}

// ---- cluster / mbarrier helpers -------------------------------------------
__device__ __forceinline__ uint32_t smem_u32(const void* p) {
    uint32_t a;
    asm("{ .reg .u64 t; cvta.to.shared.u64 t, %1; cvt.u32.u64 %0, t; }" : "=r"(a) : "l"(p));
    return a;
}
__device__ __forceinline__ uint32_t mapa32(uint32_t a, uint32_t rank) {
    uint32_t r; asm("mapa.shared::cluster.u32 %0, %1, %2;" : "=r"(r) : "r"(a), "r"(rank));
    return r;
}
__device__ __forceinline__ void st_cl_f32(uint32_t a, float v) {
    asm volatile("st.shared::cluster.f32 [%0], %1;" :: "r"(a), "f"(v) : "memory");
}
__device__ __forceinline__ void mbar_init(uint32_t a, uint32_t count) {
    asm volatile("mbarrier.init.shared.b64 [%0], %1;" :: "r"(a), "r"(count) : "memory");
}
__device__ __forceinline__ void arrive_rel_cluster(uint32_t a) {
    asm volatile("mbarrier.arrive.release.cluster.shared::cluster.b64 _, [%0];"
                 :: "r"(a) : "memory");
}
__device__ __forceinline__ void wait_parity_acq_cluster(uint32_t a, uint32_t par) {
    uint32_t done;
    asm volatile("{\n\t.reg .pred p;\n\t"
                 "mbarrier.try_wait.parity.acquire.cluster.shared::cta.b64 p, [%1], %2, 0x989680;\n\t"
                 "selp.b32 %0,1,0,p;\n\t}"
                 : "=r"(done) : "r"(a), "r"(par) : "memory");
    while (!done) {
        asm volatile("{\n\t.reg .pred p;\n\t"
                     "mbarrier.try_wait.parity.acquire.cluster.shared::cta.b64 p, [%1], %2, 0x989680;\n\t"
                     "selp.b32 %0,1,0,p;\n\t}"
                     : "=r"(done) : "r"(a), "r"(par) : "memory");
    }
}
#define CLUSTER_SYNC_() do { \
    asm volatile("barrier.cluster.arrive.aligned;" ::: "memory"); \
    asm volatile("barrier.cluster.wait.aligned;" ::: "memory"); } while (0)

// ---------------------------------------------------------------------------
// Weight prep
// ---------------------------------------------------------------------------
__global__ void prep_wih_kernel(const float* __restrict__ w0f, const float* __restrict__ w0b,
                                const float* __restrict__ w1f, const float* __restrict__ w1b)
{
    int idx = blockIdx.x * blockDim.x + threadIdx.x;
    const int N0 = 2 * INn * G4;
    const int N1 = 2 * F2n * G4;
    if (idx < N0) {
        int d = idx / (INn * G4), r = idx % (INn * G4);
        int i = r / G4, g = r % G4;
        g_wihT0[d][i][g] = (d ? w0b : w0f)[g * INn + i];
    } else if (idx < N0 + N1) {
        int r2 = idx - N0;
        int d = r2 / (F2n * G4), r = r2 % (F2n * G4);
        int i = r / G4, g = r % G4;
        g_wihT1[d][i][g] = (d ? w1b : w1f)[g * F2n + i];
    }
}

__global__ void prep_score_kernel(const float* __restrict__ w_s1,
                                  const float* __restrict__ w_c1,
                                  const float* __restrict__ w_b1)
{
    int idx = blockIdx.x * blockDim.x + threadIdx.x;
    const int NA = F2n * 128;
    const int NB = F2n * 80;
    if (idx < NA) {
        int t = idx >> 7, ph = idx & 127;
        g_w1cT[t][ph] = (ph < PHn) ? w_s1[ph * 768 + t] : 0.f;
    } else if (idx < 2 * NA) {
        int r = idx - NA; int t = r >> 7, ph = r & 127;
        g_w1dT[t][ph] = (ph < PHn) ? w_s1[ph * 768 + 256 + t] : 0.f;
    } else if (idx < 3 * NA) {
        int r = idx - 2 * NA; int t = r >> 7, ph = r & 127;
        g_w1eT[t][ph] = (ph < PHn) ? w_s1[ph * 768 + 512 + t] : 0.f;
    } else if (idx < 3 * NA + NB) {
        int r = idx - 3 * NA; int t = r / 80, q = r % 80;
        g_wc1T[t][q] = w_c1[q * F2n + t];
    } else if (idx < 3 * NA + 2 * NB) {
        int r = idx - 3 * NA - NB; int t = r / 80, q = r % 80;
        g_wb1T[t][q] = w_b1[q * F2n + t];
    }
}

// ---------------------------------------------------------------------------
// pre: gate pre-activations, scalar layout row = gate*128+unit
// ---------------------------------------------------------------------------
__global__ void pre_kernel(const float* __restrict__ x, int layer,
                           const float* __restrict__ bf, const float* __restrict__ bb)
{
    int s = blockIdx.x, b = blockIdx.y, d = blockIdx.z;
    int g = threadIdx.x;                       // 512 threads; g = gate*128+unit
    int in_dim = layer ? F2n : INn;
    const float* row = layer ? &g_out0[b][s][0] : (x + (b * Sn + s) * INn);
    const float* wT = layer ? &g_wihT1[d][0][0] : &g_wihT0[d][0][0];

    __shared__ float xs[F2n];
    for (int i = g; i < in_dim; i += blockDim.x) xs[i] = row[i];
    __syncthreads();

    float acc = (d ? bb : bf)[g];
    #pragma unroll 8
    for (int i = 0; i < in_dim; i++) acc += wT[i * G4 + g] * xs[i];

    g_preG[d][b][s][g] = acc;
}

// ---------------------------------------------------------------------------
// LSTM scan: cluster of 4 CTAs per (layer, dir, BATCH). CTA r owns units
// [32r,32r+32) with FULL k range, ONE batch. Weights in registers.
// 256 threads: t -> (kh = t>>7, row = t&127), row = gate*32 + u.
// Per step: 64 FFMA/thread -> pall -> __syncthreads -> warp0 epilogue
// (32 units: reduce 2 halves, c/h update, 128B h-broadcast to 4 ranks,
// __syncwarp, lanes 0..3 release-arrive). One syncthreads per step.
// ---------------------------------------------------------------------------
__global__ void __cluster_dims__(CL, 1, 1) __launch_bounds__(256, 1)
scan_kernel(int layer, const float* __restrict__ whhF, const float* __restrict__ whhB)
{
    int r = blockIdx.x;           // cluster rank (unit group)
    int d = blockIdx.y;           // direction
    int b = blockIdx.z;           // batch
    int t = threadIdx.x;          // 0..255
    int row = t & 127;            // gate*32 + u
    int kh  = t >> 7;             // k half
    int gate = row >> 5, u = row & 31;

    __shared__ __align__(16) float hbuf[2][Hn];   // [parity][k]
    __shared__ float pall[2][128];                // [kh][row]
    __shared__ __align__(8) unsigned long long mbar[2];

    uint32_t barL = smem_u32(&mbar[0]);
    if (t == 0) { mbar_init(barL, CL); mbar_init(barL + 8, CL); }
    if (t < Hn) { hbuf[0][t] = 0.f; hbuf[1][t] = 0.f; }

    // load this thread's weight row half into registers (once)
    const float* whh = d ? whhB : whhF;
    const float4* wsrc = (const float4*)(whh + (gate * Hn + r * 32 + u) * Hn + kh * 64);
    float4 w[16];
    #pragma unroll
    for (int q = 0; q < 16; q++) w[q] = wsrc[q];

    __syncthreads();
    CLUSTER_SYNC_();

    float* out = layer ? &g_rnn[0][0][0] : &g_out0[0][0][0];
    const float* preB = &g_preG[d][b][0][0];          // [s][512]
    int prow = gate * Hn + r * 32 + u;
    float pm = kh ? 0.f : 1.f;                        // only kh==0 carries pre

    // epilogue mapping (warp 0): eu = t (t<32)
    float cst = 0.f;
    uint32_t hA = smem_u32(&hbuf[0][r * 32 + (t & 31)]);
    uint32_t hD0 = mapa32(hA, 0), hD1 = mapa32(hA, 1),
             hD2 = mapa32(hA, 2), hD3 = mapa32(hA, 3);
    uint32_t barArr = (t < CL) ? mapa32(barL, (uint32_t)t) : 0u;
    const uint32_t HST = (uint32_t)(Hn * sizeof(float));   // parity stride

    unsigned wp0 = 0, wp1 = 0;

    int sf = d ? (Sn - 1) : 0;
    float pr = preB[sf * G4 + prow] * pm;

    for (int n = 0; n < Sn; n++) {
        int p = n & 1;
        if (n) {
            if (p) { wait_parity_acq_cluster(barL + 8, wp1); wp1 ^= 1; }
            else   { wait_parity_acq_cluster(barL,     wp0); wp0 ^= 1; }
        }
        int s = d ? (Sn - 1 - n) : n;

        const float4* h4 = (const float4*)&hbuf[p][kh * 64];
        float a = pr;
        #pragma unroll
        for (int q = 0; q < 16; q++) {
            float4 wq = w[q];
            float4 v = h4[q];
            a += wq.x * v.x + wq.y * v.y + wq.z * v.z + wq.w * v.w;
        }
        pall[kh][row] = a;

        // prefetch next step's pre (latency hides under epilogue/wait)
        if (n + 1 < Sn) {
            int sn = d ? (Sn - 2 - n) : (n + 1);
            pr = preB[sn * G4 + prow] * pm;
        }
        __syncthreads();

        if (t < 32) {
            float gi = pall[0][t]      + pall[1][t];
            float gf = pall[0][32 + t] + pall[1][32 + t];
            float gg = pall[0][64 + t] + pall[1][64 + t];
            float go = pall[0][96 + t] + pall[1][96 + t];
            cst = sigf(gf) * cst + sigf(gi) * tanh_fast(gg);
            float h = sigf(go) * tanh_fast(cst);
            out[(b * Sn + s) * F2n + d * Hn + (r * 32 + t)] = h;
            uint32_t off = (uint32_t)(p ^ 1) * HST;
            st_cl_f32(hD0 + off, h);
            st_cl_f32(hD1 + off, h);
            st_cl_f32(hD2 + off, h);
            st_cl_f32(hD3 + off, h);
            __syncwarp();
            if (t < CL) arrive_rel_cluster(barArr + (uint32_t)(p ^ 1) * 8u);
        }
    }
    CLUSTER_SYNC_();
}

// ---------------------------------------------------------------------------
__global__ void cum_kernel()
{
    int b = blockIdx.x, t = threadIdx.x;       // 256 threads
    float acc = 0.f;
    for (int s = 0; s < Sn; s++) { acc += g_rnn[b][s][t]; g_cum[b][s][t] = acc; }
}

// ---------------------------------------------------------------------------
// Per-position u/v projections + cls/bin heads
// ---------------------------------------------------------------------------
__global__ void feat_kernel(const float* __restrict__ a_s0p,
                            const float* __restrict__ a_c0p, const float* __restrict__ b_c1,
                            const float* __restrict__ a_c1p, const float* __restrict__ w_c2,
                            const float* __restrict__ b_c2,
                            const float* __restrict__ a_b0p, const float* __restrict__ b_b1,
                            const float* __restrict__ a_b1p, const float* __restrict__ w_b2,
                            const float* __restrict__ b_b2,
                            float* __restrict__ out)
{
    int s = blockIdx.x, b = blockIdx.y, tid = threadIdx.x;   // 128 threads
    __shared__ float prs[F2n], prc[F2n], prb[F2n];
    __shared__ float hc[80], hb[80];
    float as0 = *a_s0p, ac0 = *a_c0p, ac1 = *a_c1p, ab0 = *a_b0p, ab1 = *a_b1p;

    for (int i = tid; i < F2n; i += 128) {
        float xv = g_rnn[b][s][i];
        prs[i] = xv >= 0.f ? xv : as0 * xv;
        prc[i] = xv >= 0.f ? xv : ac0 * xv;
        prb[i] = xv >= 0.f ? xv : ab0 * xv;
    }
    __syncthreads();

    if (tid < PHn) {
        float au = 0.f, av = 0.f;
        #pragma unroll 8
        for (int i = 0; i < F2n; i++) {
            float p = prs[i];
            au += g_w1dT[i][tid] * p;
            av += g_w1eT[i][tid] * p;
        }
        g_u[b][s][tid] = au;
        g_v[b][s][tid] = av;
    }
    if (tid < 80) {
        float a1 = b_c1[tid], a2 = b_b1[tid];
        #pragma unroll 8
        for (int i = 0; i < F2n; i++) {
            a1 += g_wc1T[i][tid] * prc[i];
            a2 += g_wb1T[i][tid] * prb[i];
        }
        hc[tid] = a1 >= 0.f ? a1 : ac1 * a1;
        hb[tid] = a2 >= 0.f ? a2 : ab1 * a2;
    }
    __syncthreads();
    if (tid < NCn) {
        float acc = b_c2[tid];
        const float* w = w_c2 + tid * 80;
        #pragma unroll 8
        for (int i = 0; i < 80; i++) acc += w[i] * hc[i];
        out[(b * Sn + s) * NCn + tid] = acc;
    }
    if (tid < 2) {
        float acc = b_b2[tid];
        const float* w = w_b2 + tid * 80;
        for (int i = 0; i < 80; i++) acc += w[i] * hb[i];
        out[Bn * Sn * NCn + (b * Sn + s) * 2 + tid] = acc;
    }
}

// ---------------------------------------------------------------------------
// Banded scores, one CTA per (b, i)
// ---------------------------------------------------------------------------
__global__ void __launch_bounds__(128) sband_kernel(
        const float* __restrict__ a_s0p, const float* __restrict__ b_s1,
        const float* __restrict__ a_s1p, const float* __restrict__ w_s2,
        const float* __restrict__ b_s2)
{
    int i = blockIdx.x + 1, b = blockIdx.y, tid = threadIdx.x;  // 128 threads
    int start = i - Wn; if (start < 0) start = 0;

    __shared__ __align__(16) float pd[Wn * TP];
    float acc[Wn];
    #pragma unroll
    for (int j = 0; j < Wn; j++) acc[j] = 0.f;

    float as0 = *a_s0p;

    for (int pass = 0; pass < 2; pass++) {
        int tb = pass * 128;
        float cI = g_cum[b][i][tb + tid];
        for (int j = 0; j < Wn; j++) {
            float dc = cI - g_cum[b][start + j][tb + tid];
            pd[j * TP + tid] = dc >= 0.f ? dc : as0 * dc;
        }
        __syncthreads();

        for (int t0 = 0; t0 < 128; t0 += 4) {
            float w0 = g_w1cT[tb + t0][tid];
            float w1 = g_w1cT[tb + t0 + 1][tid];
            float w2 = g_w1cT[tb + t0 + 2][tid];
            float w3 = g_w1cT[tb + t0 + 3][tid];
            #pragma unroll
            for (int j = 0; j < Wn; j++) {
                float4 p = *(const float4*)&pd[j * TP + t0];
                acc[j] += w0 * p.x + w1 * p.y + w2 * p.z + w3 * p.w;
            }
        }
        __syncthreads();
    }

    float* red = pd;
    float wsc  = tid < PHn ? w_s2[tid] : 0.f;
    float bs1v = tid < PHn ? b_s1[tid] : 0.f;
    float vi   = tid < PHn ? g_v[b][i][tid] : 0.f;
    float as1  = *a_s1p;

    for (int j = 0; j < Wn; j++) {
        if (tid < PHn) {
            float uj = g_u[b][start + j][tid];
            float hs = acc[j] + bs1v + uj + vi;
            float pr = hs >= 0.f ? hs : as1 * hs;
            red[j * 101 + tid] = pr * wsc;
        }
    }
    __syncthreads();
    if (tid < Wn) {
        float s = *b_s2;
        #pragma unroll 4
        for (int p = 0; p < PHn; p++) s += red[tid * 101 + p];
        g_sband[b][i][tid] = s;
    }
}

// ---------------------------------------------------------------------------
// DP + backtrack: one warp per batch, no __syncthreads in the hot loop.
// ---------------------------------------------------------------------------
__global__ void dp_kernel(const int* __restrict__ lengths, float* __restrict__ out)
{
    int tid = threadIdx.x;                     // 64 threads = 2 warps
    int b = tid >> 5, lane = tid & 31;
    __shared__ float best[Bn][Sn];
    __shared__ float esc[Bn][Sn];
    __shared__ int   bpS[Bn][Sn];

    for (int idx = tid; idx < Bn * Sn; idx += 64) ((float*)best)[idx] = 0.f;
    __syncthreads();

    float sa  = g_sband[b][1][lane];
    float sb2 = g_sband[b][1][lane + 32];
    for (int i = 1; i < Sn; i++) {
        float s0 = sa, s1 = sb2;
        if (i + 1 < Sn) { sa = g_sband[b][i + 1][lane]; sb2 = g_sband[b][i + 1][lane + 32]; }
        int start = i - Wn; if (start < 0) start = 0;
        int j0 = start + lane, j1 = start + lane + 32;
        unsigned long long key = 0ull;
        float v0 = 0.f, v1 = 0.f;
        if (j0 < i) {
            v0 = best[b][j0] + s0;
            unsigned u = __float_as_uint(v0);
            u = (u & 0x80000000u) ? ~u : (u | 0x80000000u);
            key = ((unsigned long long)u << 32) | (unsigned)(0xFFFFFFFFu - (unsigned)j0);
        }
        if (j1 < i) {
            v1 = best[b][j1] + s1;
            unsigned u = __float_as_uint(v1);
            u = (u & 0x80000000u) ? ~u : (u | 0x80000000u);
            unsigned long long k1 = ((unsigned long long)u << 32) | (unsigned)(0xFFFFFFFFu - (unsigned)j1);
            if (k1 > key) key = k1;
        }
        #pragma unroll
        for (int off = 16; off; off >>= 1) {
            unsigned long long ok = __shfl_down_sync(0xffffffffu, key, off);
            if (ok > key) key = ok;
        }
        key = __shfl_sync(0xffffffffu, key, 0);
        int jstar = (int)(0xFFFFFFFFu - (unsigned)(key & 0xFFFFFFFFull));
        if (j0 == jstar && j0 < i) { best[b][i] = v0; bpS[b][i] = jstar; esc[b][i] = s0; }
        if (j1 == jstar && j1 < i) { best[b][i] = v1; bpS[b][i] = jstar; esc[b][i] = s1; }
        __syncwarp();
    }
    __syncthreads();

    // ---- backtrack ----
    float* bm = out + Bn * Sn * NCn + Bn * Sn * 2;
    for (int idx = tid; idx < Bn * Sn; idx += 64) bm[idx] = 0.f;
    if (tid < Bn) { bpS[tid][0] = 0; esc[tid][0] = 0.f; }
    __syncthreads();
    if (lane == 0) {
        int cur = lengths[b] - 1;
        float acc = 0.f;
        for (int st2 = 0; st2 < Sn; st2++) {
            bm[b * Sn + cur] = 1.0f;
            int prev = bpS[b][cur];
            if (cur > 0) { acc += esc[b][cur]; cur = prev; }
        }
        out[Bn * Sn * NCn + Bn * Sn * 2 + Bn * Sn + b] = acc;
    }
}

// ---------------------------------------------------------------------------
extern "C" void kernel_launch(void* const* d_in, const int* in_sizes, int n_in,
                              void* d_out, int out_size)
{
    const float* x        = (const float*)d_in[0];
    const int*   lengths  = (const int*)  d_in[1];
    const float* w_ih_l0f = (const float*)d_in[2];
    const float* w_hh_l0f = (const float*)d_in[3];
    const float* b_l0f    = (const float*)d_in[4];
    const float* w_ih_l0b = (const float*)d_in[5];
    const float* w_hh_l0b = (const float*)d_in[6];
    const float* b_l0b    = (const float*)d_in[7];
    const float* w_ih_l1f = (const float*)d_in[8];
    const float* w_hh_l1f = (const float*)d_in[9];
    const float* b_l1f    = (const float*)d_in[10];
    const float* w_ih_l1b = (const float*)d_in[11];
    const float* w_hh_l1b = (const float*)d_in[12];
    const float* b_l1b    = (const float*)d_in[13];
    const float* a_s0     = (const float*)d_in[14];
    const float* w_s1     = (const float*)d_in[15];
    const float* b_s1     = (const float*)d_in[16];
    const float* a_s1     = (const float*)d_in[17];
    const float* w_s2     = (const float*)d_in[18];
    const float* b_s2     = (const float*)d_in[19];
    const float* a_c0     = (const float*)d_in[20];
    const float* w_c1     = (const float*)d_in[21];
    const float* b_c1     = (const float*)d_in[22];
    const float* a_c1     = (const float*)d_in[23];
    const float* w_c2     = (const float*)d_in[24];
    const float* b_c2     = (const float*)d_in[25];
    const float* a_b0     = (const float*)d_in[26];
    const float* w_b1     = (const float*)d_in[27];
    const float* b_b1     = (const float*)d_in[28];
    const float* a_b1     = (const float*)d_in[29];
    const float* w_b2     = (const float*)d_in[30];
    const float* b_b2     = (const float*)d_in[31];
    float* out = (float*)d_out;

    // launches ordered so that ncu (-s 5 -c 1) captures scan_kernel(layer 1)
    prep_wih_kernel<<<(2 * INn * G4 + 2 * F2n * G4 + 255) / 256, 256>>>(
        w_ih_l0f, w_ih_l0b, w_ih_l1f, w_ih_l1b);                                       // 1
    pre_kernel<<<dim3(Sn, Bn, 2), G4>>>(x, 0, b_l0f, b_l0b);                           // 2
    scan_kernel<<<dim3(CL, 2, Bn), 256>>>(0, w_hh_l0f, w_hh_l0b);                      // 3
    pre_kernel<<<dim3(Sn, Bn, 2), G4>>>(x, 1, b_l1f, b_l1b);                           // 4
    prep_score_kernel<<<(3 * F2n * 128 + 2 * F2n * 80 + 255) / 256, 256>>>(w_s1, w_c1, w_b1); // 5
    scan_kernel<<<dim3(CL, 2, Bn), 256>>>(1, w_hh_l1f, w_hh_l1b);                      // 6 <- profiled
    cum_kernel<<<Bn, F2n>>>();                                                         // 7
    feat_kernel<<<dim3(Sn, Bn), 128>>>(a_s0, a_c0, b_c1, a_c1, w_c2, b_c2,
                                       a_b0, b_b1, a_b1, w_b2, b_b2, out);             // 8
    sband_kernel<<<dim3(Sn - 1, Bn), 128>>>(a_s0, b_s1, a_s1, w_s2, b_s2);             // 9
    dp_kernel<<<1, 64>>>(lengths, out);                                                // 10
}